// round 1
// baseline (speedup 1.0000x reference)
#include <cuda_runtime.h>
#include <math.h>

#define MTOT 4096      // B*T
#define TLEN 2048
#define HQ   8
#define DKh  256
#define DVh  512
#define HID  2048
#define NQK  2048      // H*DK
#define NVG  4096      // H*DV

// scratch: q(8.39M) k(8.39M) v(16.78M) g(16.78M) o(16.78M) = 64M floats = 256MB
__device__ float g_scratch[67108864];

// ---------------- SGEMM: C[M,N] = A[M,K] @ B[K,N], all row-major, dims %128/%8 ----------------
__global__ __launch_bounds__(256) void sgemm_k(const float* __restrict__ A,
                                               const float* __restrict__ B,
                                               float* __restrict__ C,
                                               int M, int N, int K) {
    __shared__ float As[8][128];
    __shared__ float Bs[8][128];
    const int t = threadIdx.x;
    const int bx = blockIdx.x, by = blockIdx.y;
    const int aRow = t >> 1;            // 0..127
    const int aCol = (t & 1) << 2;      // 0 or 4
    const int bRow = t >> 5;            // 0..7
    const int bCol = (t & 31) << 2;     // 0..124
    const int tx = t & 15, ty = t >> 4;
    const float* Ap = A + (size_t)(by * 128 + aRow) * K + aCol;
    const float* Bp = B + (size_t)bRow * N + bx * 128 + bCol;
    float acc[8][8];
#pragma unroll
    for (int i = 0; i < 8; i++)
#pragma unroll
        for (int j = 0; j < 8; j++) acc[i][j] = 0.f;

    for (int k0 = 0; k0 < K; k0 += 8) {
        float4 a4 = *(const float4*)(Ap + k0);
        float4 b4 = *(const float4*)(Bp + (size_t)k0 * N);
        As[aCol + 0][aRow] = a4.x;
        As[aCol + 1][aRow] = a4.y;
        As[aCol + 2][aRow] = a4.z;
        As[aCol + 3][aRow] = a4.w;
        *(float4*)&Bs[bRow][bCol] = b4;
        __syncthreads();
#pragma unroll
        for (int kk = 0; kk < 8; kk++) {
            float ra[8], rb[8];
            *(float4*)&ra[0] = *(const float4*)&As[kk][ty * 4];
            *(float4*)&ra[4] = *(const float4*)&As[kk][ty * 4 + 64];
            *(float4*)&rb[0] = *(const float4*)&Bs[kk][tx * 4];
            *(float4*)&rb[4] = *(const float4*)&Bs[kk][tx * 4 + 64];
#pragma unroll
            for (int i = 0; i < 8; i++)
#pragma unroll
                for (int j = 0; j < 8; j++) acc[i][j] += ra[i] * rb[j];
        }
        __syncthreads();
    }
#pragma unroll
    for (int i = 0; i < 8; i++) {
        int r = by * 128 + ty * 4 + (i & 3) + ((i >> 2) << 6);
        float* Cr = C + (size_t)r * N + bx * 128;
        *(float4*)&Cr[tx * 4]      = make_float4(acc[i][0], acc[i][1], acc[i][2], acc[i][3]);
        *(float4*)&Cr[tx * 4 + 64] = make_float4(acc[i][4], acc[i][5], acc[i][6], acc[i][7]);
    }
}

// ---------------- RoPE in-place on q and k ----------------
// idx -> (bt, h, j); pairs (j, j+128) within each 256-dim head
__global__ __launch_bounds__(256) void rope_k(float* __restrict__ q, float* __restrict__ k) {
    int idx = blockIdx.x * 256 + threadIdx.x;   // 0 .. 4,194,303
    int j  = idx & 127;
    int h  = (idx >> 7) & 7;
    int bt = idx >> 10;                          // 0..4095
    int pos = bt & (TLEN - 1);
    // inv_freq = 10000^(-(2j)/256) = 2^(-j * log2(10000)/128)
    float inv = exp2f(-(float)j * (13.2877123795494f / 128.0f));
    float ph = (float)pos * inv;
    float s, c;
    sincosf(ph, &s, &c);
    size_t base = (size_t)bt * NQK + h * DKh + j;
    float x1 = q[base], x2 = q[base + 128];
    q[base]       = x1 * c - x2 * s;
    q[base + 128] = x2 * c + x1 * s;
    x1 = k[base]; x2 = k[base + 128];
    k[base]       = x1 * c - x2 * s;
    k[base + 128] = x2 * c + x1 * s;
}

// ---------------- Retention: per (b,h,i-tile of 32 rows), full DV=512 ----------------
// smem: Qs[32][260] Ks[32][260] Vs[32][512] Ss[32][33]  = 136,320 bytes
#define RET_SMEM_BYTES ((2 * 32 * 260 + 32 * 512 + 32 * 33) * 4)

__global__ __launch_bounds__(256) void retention_k(const float* __restrict__ Q,
                                                   const float* __restrict__ Kt,
                                                   const float* __restrict__ V,
                                                   float* __restrict__ O) {
    extern __shared__ float sm[];
    float* Qs = sm;                    // 32 x 260
    float* Ks = Qs + 32 * 260;         // 32 x 260
    float* Vs = Ks + 32 * 260;         // 32 x 512
    float* Ss = Vs + 32 * 512;         // 32 x 33

    const int t  = threadIdx.x;
    const int it = blockIdx.x;
    const int h  = blockIdx.y;
    const int b  = blockIdx.z;
    const int i0 = it * 32;
    const float scale = 0.0625f;                      // DK^-0.5
    const float gamma = 1.0f - exp2f(-5.0f - (float)h);
    const float l2g   = log2f(gamma);

    // load Q tile (32 x 256)
    {
        const float* Qg = Q + ((size_t)(b * TLEN + i0)) * NQK + h * DKh;
#pragma unroll
        for (int u = 0; u < 8; u++) {
            int idx = t + u * 256;              // 0..2047 float4s
            int row = idx >> 6, c4 = idx & 63;
            *(float4*)(Qs + row * 260 + c4 * 4) =
                *(const float4*)(Qg + (size_t)row * NQK + c4 * 4);
        }
    }

    const int tx = t & 31, ty = t >> 5;   // O phase mapping
    const int r_s = t & 31, jw = t >> 5;  // S phase mapping
    float4 acc[4][4];
#pragma unroll
    for (int rr = 0; rr < 4; rr++)
#pragma unroll
        for (int cb = 0; cb < 4; cb++) acc[rr][cb] = make_float4(0.f, 0.f, 0.f, 0.f);

    for (int jt = 0; jt <= it; jt++) {
        __syncthreads();   // previous O-phase done before K/V overwrite (also covers Q load)
        const int j0 = jt * 32;
        // load K tile
        const float* Kg = Kt + ((size_t)(b * TLEN + j0)) * NQK + h * DKh;
#pragma unroll
        for (int u = 0; u < 8; u++) {
            int idx = t + u * 256;
            int row = idx >> 6, c4 = idx & 63;
            *(float4*)(Ks + row * 260 + c4 * 4) =
                *(const float4*)(Kg + (size_t)row * NQK + c4 * 4);
        }
        // load V tile
        const float* Vg = V + ((size_t)(b * TLEN + j0)) * NVG + h * DVh;
#pragma unroll
        for (int u = 0; u < 16; u++) {
            int idx = t + u * 256;
            int row = idx >> 7, c4 = idx & 127;
            *(float4*)(Vs + row * 512 + c4 * 4) =
                *(const float4*)(Vg + (size_t)row * NVG + c4 * 4);
        }
        __syncthreads();

        // ---- S = (Q K^T) * scale * decay, masked ----
        float s0 = 0.f, s1 = 0.f, s2 = 0.f, s3 = 0.f;
        {
            const float4* q4 = (const float4*)(Qs + r_s * 260);
#pragma unroll 4
            for (int d4 = 0; d4 < 64; d4++) {
                float4 qv = q4[d4];
                float4 k0v = *(const float4*)(Ks + (jw * 4 + 0) * 260 + d4 * 4);
                float4 k1v = *(const float4*)(Ks + (jw * 4 + 1) * 260 + d4 * 4);
                float4 k2v = *(const float4*)(Ks + (jw * 4 + 2) * 260 + d4 * 4);
                float4 k3v = *(const float4*)(Ks + (jw * 4 + 3) * 260 + d4 * 4);
                s0 += qv.x * k0v.x + qv.y * k0v.y + qv.z * k0v.z + qv.w * k0v.w;
                s1 += qv.x * k1v.x + qv.y * k1v.y + qv.z * k1v.z + qv.w * k1v.w;
                s2 += qv.x * k2v.x + qv.y * k2v.y + qv.z * k2v.z + qv.w * k2v.w;
                s3 += qv.x * k3v.x + qv.y * k3v.y + qv.z * k3v.z + qv.w * k3v.w;
            }
        }
        {
            float sv[4] = {s0, s1, s2, s3};
#pragma unroll
            for (int u = 0; u < 4; u++) {
                int j = jw * 4 + u;
                float diff = (float)(i0 + r_s - (j0 + j));
                float w = (jt == it && j > r_s) ? 0.f : scale * exp2f(l2g * diff);
                Ss[r_s * 33 + j] = sv[u] * w;
            }
        }
        __syncthreads();

        // ---- O += S @ V ----
#pragma unroll 4
        for (int j = 0; j < 32; j++) {
            float sr0 = Ss[(ty * 4 + 0) * 33 + j];
            float sr1 = Ss[(ty * 4 + 1) * 33 + j];
            float sr2 = Ss[(ty * 4 + 2) * 33 + j];
            float sr3 = Ss[(ty * 4 + 3) * 33 + j];
#pragma unroll
            for (int cb = 0; cb < 4; cb++) {
                float4 vv = *(const float4*)(Vs + j * 512 + tx * 4 + cb * 128);
                acc[0][cb].x += sr0 * vv.x; acc[0][cb].y += sr0 * vv.y;
                acc[0][cb].z += sr0 * vv.z; acc[0][cb].w += sr0 * vv.w;
                acc[1][cb].x += sr1 * vv.x; acc[1][cb].y += sr1 * vv.y;
                acc[1][cb].z += sr1 * vv.z; acc[1][cb].w += sr1 * vv.w;
                acc[2][cb].x += sr2 * vv.x; acc[2][cb].y += sr2 * vv.y;
                acc[2][cb].z += sr2 * vv.z; acc[2][cb].w += sr2 * vv.w;
                acc[3][cb].x += sr3 * vv.x; acc[3][cb].y += sr3 * vv.y;
                acc[3][cb].z += sr3 * vv.z; acc[3][cb].w += sr3 * vv.w;
            }
        }
    }

    // write O tile
    float* Og = O + ((size_t)(b * TLEN + i0 + ty * 4)) * NVG + h * DVh;
#pragma unroll
    for (int rr = 0; rr < 4; rr++)
#pragma unroll
        for (int cb = 0; cb < 4; cb++)
            *(float4*)(Og + (size_t)rr * NVG + tx * 4 + cb * 128) = acc[rr][cb];
}

// ---------------- RMS norm (over DV) + SiLU gate, in-place on o ----------------
__global__ __launch_bounds__(256) void rmsgate_k(float* __restrict__ o,
                                                 const float* __restrict__ g,
                                                 const float* __restrict__ w) {
    int warp = (blockIdx.x * 256 + threadIdx.x) >> 5;  // 0..32767 = bt*8 + h
    int lane = threadIdx.x & 31;
    size_t base = (size_t)(warp >> 3) * NVG + (size_t)(warp & 7) * DVh;
    float ov[16];
    float ss = 0.f;
#pragma unroll
    for (int u = 0; u < 16; u++) {
        ov[u] = o[base + lane + u * 32];
        ss += ov[u] * ov[u];
    }
#pragma unroll
    for (int off = 16; off; off >>= 1) ss += __shfl_xor_sync(0xFFFFFFFFu, ss, off);
    float r = rsqrtf(ss * (1.0f / 512.0f) + 1e-5f);
#pragma unroll
    for (int u = 0; u < 16; u++) {
        int c = lane + u * 32;
        float gv = g[base + c];
        float gate = gv / (1.f + expf(-gv));   // g * sigmoid(g)
        o[base + c] = ov[u] * r * w[c] * gate;
    }
}

extern "C" void kernel_launch(void* const* d_in, const int* in_sizes, int n_in,
                              void* d_out, int out_size) {
    const float* X   = (const float*)d_in[0];
    const float* Wq  = (const float*)d_in[1];
    const float* Wk  = (const float*)d_in[2];
    const float* Wv  = (const float*)d_in[3];
    const float* Wg  = (const float*)d_in[4];
    const float* Wo  = (const float*)d_in[5];
    const float* gnw = (const float*)d_in[6];
    float* out = (float*)d_out;

    float* base = nullptr;
    cudaGetSymbolAddress((void**)&base, g_scratch);
    float* dq = base;
    float* dk = dq + (size_t)MTOT * NQK;
    float* dv = dk + (size_t)MTOT * NQK;
    float* dg = dv + (size_t)MTOT * NVG;
    float* dro = dg + (size_t)MTOT * NVG;

    dim3 thr(256);
    sgemm_k<<<dim3(NQK / 128, MTOT / 128), thr>>>(X, Wq, dq, MTOT, NQK, HID);
    sgemm_k<<<dim3(NQK / 128, MTOT / 128), thr>>>(X, Wk, dk, MTOT, NQK, HID);
    sgemm_k<<<dim3(NVG / 128, MTOT / 128), thr>>>(X, Wv, dv, MTOT, NVG, HID);
    sgemm_k<<<dim3(NVG / 128, MTOT / 128), thr>>>(X, Wg, dg, MTOT, NVG, HID);

    rope_k<<<16384, 256>>>(dq, dk);

    cudaFuncSetAttribute(retention_k, cudaFuncAttributeMaxDynamicSharedMemorySize,
                         RET_SMEM_BYTES);
    retention_k<<<dim3(TLEN / 32, HQ, 2), thr, RET_SMEM_BYTES>>>(dq, dk, dv, dro);

    rmsgate_k<<<4096, 256>>>(dro, dg, gnw);

    sgemm_k<<<dim3(HID / 128, MTOT / 128), thr>>>(dro, Wo, out, MTOT, HID, NVG);
}

// round 5
// speedup vs baseline: 1.6111x; 1.6111x over previous
#include <cuda_runtime.h>
#include <cuda_bf16.h>
#include <stdint.h>
#include <cstdint>
#include <math.h>

#define MTOT 4096      // B*T
#define TLEN 2048
#define HQ   8
#define DKh  256
#define DVh  512
#define HID  2048
#define NQK  2048      // H*DK
#define NVG  4096      // H*DV

// ---------------- big device pool (allocation-free scratch) ----------------
__device__ __align__(1024) unsigned char g_pool[528482304];

__device__ __forceinline__ uint32_t smem_to_u32(const void* p) {
    uint32_t a;
    asm("{ .reg .u64 t; cvta.to.shared.u64 t, %1; cvt.u32.u64 %0, t; }"
        : "=r"(a) : "l"(p));
    return a;
}
#define SMEM_SWIZZLE_128B(byte_offset) \
    ((byte_offset) ^ (((byte_offset) >> 3) & 0x70))

// -------- mma.sync / ldmatrix helpers (generic sm_80+ PTX, sm_103-safe) --------
__device__ __forceinline__ void ldmx4(uint32_t& r0, uint32_t& r1, uint32_t& r2,
                                      uint32_t& r3, uint32_t addr) {
    asm volatile("ldmatrix.sync.aligned.m8n8.x4.shared.b16 {%0,%1,%2,%3}, [%4];"
                 : "=r"(r0), "=r"(r1), "=r"(r2), "=r"(r3) : "r"(addr));
}
__device__ __forceinline__ void ldmx2(uint32_t& r0, uint32_t& r1, uint32_t addr) {
    asm volatile("ldmatrix.sync.aligned.m8n8.x2.shared.b16 {%0,%1}, [%2];"
                 : "=r"(r0), "=r"(r1) : "r"(addr));
}
__device__ __forceinline__ void mma16816(float& c0, float& c1, float& c2, float& c3,
                                         uint32_t a0, uint32_t a1, uint32_t a2,
                                         uint32_t a3, uint32_t b0, uint32_t b1) {
    asm volatile(
        "mma.sync.aligned.m16n8k16.row.col.f32.bf16.bf16.f32 "
        "{%0,%1,%2,%3}, {%4,%5,%6,%7}, {%8,%9}, {%0,%1,%2,%3};"
        : "+f"(c0), "+f"(c1), "+f"(c2), "+f"(c3)
        : "r"(a0), "r"(a1), "r"(a2), "r"(a3), "r"(b0), "r"(b1));
}

// ================= HMMA GEMM: C[M,N] = A[M,K] @ B[K,N] =================
// Operands pre-split to bf16 hi/lo.  Ah/Al: [M,K] row-major.  Bh/Bl: [N,K]
// row-major (B transposed => mma "col" operand).  C ~= AhBh + AhBl + AlBh.
// CTA tile 128x128, K-chunk 64 (128B SW128 rows), double-buffered smem.
// 8 warps in 2(M) x 4(N): warp tile 64x32 = 4x4 m16n8 frags.
#define GEMM_TILE_BYTES 16384                 // 128 rows x 128 B
#define GEMM_STAGE_BYTES (4 * GEMM_TILE_BYTES)
#define GEMM_SMEM (2 * GEMM_STAGE_BYTES)      // 131072

__global__ __launch_bounds__(256, 1) void gemm_mma(
    const __nv_bfloat16* __restrict__ Ah, const __nv_bfloat16* __restrict__ Al,
    const __nv_bfloat16* __restrict__ Bh, const __nv_bfloat16* __restrict__ Bl,
    float* __restrict__ C, int M, int N, int K) {
    extern __shared__ char smem[];
    const uint32_t sb = smem_to_u32(smem);
    const int tid  = threadIdx.x;
    const int wid  = tid >> 5, lane = tid & 31;
    const int wm   = (wid & 1) * 64;      // warp M offset in tile
    const int wn   = (wid >> 1) * 32;     // warp N offset in tile

    const size_t aRow = (size_t)blockIdx.y * 128;
    const size_t bRow = (size_t)blockIdx.x * 128;
    const __nv_bfloat16* srcs[4] = {Ah + aRow * K, Al + aRow * K,
                                    Bh + bRow * K, Bl + bRow * K};
    const int KC = K >> 6;

    // ldmatrix per-lane row/k offsets
    const int a_r = (lane & 7) + ((lane >> 3) & 1) * 8;   // + m16 base
    const int a_k = (lane >> 4) * 8;                      // 0 or 8
    const int b_r = lane & 7;                             // + n8 base
    const int b_k = ((lane >> 3) & 1) * 8;                // 0 or 8 (lanes 0-15 used)

    float acc[4][4][4];
#pragma unroll
    for (int mt = 0; mt < 4; mt++)
#pragma unroll
        for (int nt = 0; nt < 4; nt++)
#pragma unroll
            for (int e = 0; e < 4; e++) acc[mt][nt][e] = 0.f;

    // prologue: stage 0
    {
        char* stage = smem;
#pragma unroll
        for (int t4 = 0; t4 < 4; t4++) {
            const __nv_bfloat16* src = srcs[t4];
            char* dst = stage + t4 * GEMM_TILE_BYTES;
#pragma unroll
            for (int u = 0; u < 4; u++) {
                int idx = tid + u * 256;
                int r = idx >> 3, c = idx & 7;
                uint4 v = *(const uint4*)(src + (size_t)r * K + c * 8);
                *(uint4*)(dst + SMEM_SWIZZLE_128B(r * 128 + c * 16)) = v;
            }
        }
    }
    __syncthreads();

    for (int kc = 0; kc < KC; kc++) {
        // prefetch next chunk into the other buffer
        if (kc + 1 < KC) {
            char* stage = smem + ((kc + 1) & 1) * GEMM_STAGE_BYTES;
#pragma unroll
            for (int t4 = 0; t4 < 4; t4++) {
                const __nv_bfloat16* src = srcs[t4] + (kc + 1) * 64;
                char* dst = stage + t4 * GEMM_TILE_BYTES;
#pragma unroll
                for (int u = 0; u < 4; u++) {
                    int idx = tid + u * 256;
                    int r = idx >> 3, c = idx & 7;
                    uint4 v = *(const uint4*)(src + (size_t)r * K + c * 8);
                    *(uint4*)(dst + SMEM_SWIZZLE_128B(r * 128 + c * 16)) = v;
                }
            }
        }

        // compute current chunk
        const uint32_t base = sb + (kc & 1) * GEMM_STAGE_BYTES;
        const uint32_t tAh = base;
        const uint32_t tAl = base + GEMM_TILE_BYTES;
        const uint32_t tBh = base + 2 * GEMM_TILE_BYTES;
        const uint32_t tBl = base + 3 * GEMM_TILE_BYTES;
#pragma unroll
        for (int ks = 0; ks < 4; ks++) {
            const int k0 = ks * 16;
            uint32_t bh[4][2], bl[4][2];
#pragma unroll
            for (int nt = 0; nt < 4; nt++) {
                int row = wn + nt * 8 + b_r;
                uint32_t off = SMEM_SWIZZLE_128B(row * 128 + (k0 + b_k) * 2);
                ldmx2(bh[nt][0], bh[nt][1], tBh + off);
                ldmx2(bl[nt][0], bl[nt][1], tBl + off);
            }
#pragma unroll
            for (int mt = 0; mt < 4; mt++) {
                int rowA = wm + mt * 16 + a_r;
                uint32_t offA = SMEM_SWIZZLE_128B(rowA * 128 + (k0 + a_k) * 2);
                uint32_t a0, a1, a2, a3;
                ldmx4(a0, a1, a2, a3, tAh + offA);
#pragma unroll
                for (int nt = 0; nt < 4; nt++)
                    mma16816(acc[mt][nt][0], acc[mt][nt][1], acc[mt][nt][2],
                             acc[mt][nt][3], a0, a1, a2, a3, bh[nt][0], bh[nt][1]);
#pragma unroll
                for (int nt = 0; nt < 4; nt++)
                    mma16816(acc[mt][nt][0], acc[mt][nt][1], acc[mt][nt][2],
                             acc[mt][nt][3], a0, a1, a2, a3, bl[nt][0], bl[nt][1]);
                uint32_t l0, l1, l2, l3;
                ldmx4(l0, l1, l2, l3, tAl + offA);
#pragma unroll
                for (int nt = 0; nt < 4; nt++)
                    mma16816(acc[mt][nt][0], acc[mt][nt][1], acc[mt][nt][2],
                             acc[mt][nt][3], l0, l1, l2, l3, bh[nt][0], bh[nt][1]);
            }
        }
        __syncthreads();
    }

    // epilogue: direct fp32 stores
#pragma unroll
    for (int mt = 0; mt < 4; mt++) {
        size_t m0 = aRow + wm + mt * 16 + (lane >> 2);
#pragma unroll
        for (int nt = 0; nt < 4; nt++) {
            size_t n0 = bRow + wn + nt * 8 + (lane & 3) * 2;
            *(float2*)(C + m0 * N + n0)       = make_float2(acc[mt][nt][0], acc[mt][nt][1]);
            *(float2*)(C + (m0 + 8) * N + n0) = make_float2(acc[mt][nt][2], acc[mt][nt][3]);
        }
    }
}

// ------------- fp32 -> bf16 hi/lo split (same layout) -------------
__global__ __launch_bounds__(256) void split_k(const float* __restrict__ in,
                                               __nv_bfloat16* __restrict__ h,
                                               __nv_bfloat16* __restrict__ l) {
    int i = (blockIdx.x * 256 + threadIdx.x) * 4;
    float4 v = *(const float4*)(in + i);
    float x;
    __nv_bfloat16 hv[4], lv[4];
    x = v.x; hv[0] = __float2bfloat16(x); lv[0] = __float2bfloat16(x - __bfloat162float(hv[0]));
    x = v.y; hv[1] = __float2bfloat16(x); lv[1] = __float2bfloat16(x - __bfloat162float(hv[1]));
    x = v.z; hv[2] = __float2bfloat16(x); lv[2] = __float2bfloat16(x - __bfloat162float(hv[2]));
    x = v.w; hv[3] = __float2bfloat16(x); lv[3] = __float2bfloat16(x - __bfloat162float(hv[3]));
    *(uint2*)(h + i) = *(uint2*)hv;
    *(uint2*)(l + i) = *(uint2*)lv;
}

// ------------- fp32 [K,N] -> bf16 hi/lo transposed [N,K] -------------
__global__ __launch_bounds__(256) void splitT_k(const float* __restrict__ in,
                                                __nv_bfloat16* __restrict__ hT,
                                                __nv_bfloat16* __restrict__ lT,
                                                int K, int N) {
    __shared__ float ts[32][33];
    int n0 = blockIdx.x * 32, k0 = blockIdx.y * 32;
    int tx = threadIdx.x & 31, ty = threadIdx.x >> 5;  // 32 x 8
#pragma unroll
    for (int r = 0; r < 4; r++)
        ts[ty + r * 8][tx] = in[(size_t)(k0 + ty + r * 8) * N + n0 + tx];
    __syncthreads();
#pragma unroll
    for (int r = 0; r < 4; r++) {
        int n = n0 + ty + r * 8, kk = k0 + tx;
        float x = ts[tx][ty + r * 8];
        __nv_bfloat16 hi = __float2bfloat16(x);
        hT[(size_t)n * K + kk] = hi;
        lT[(size_t)n * K + kk] = __float2bfloat16(x - __bfloat162float(hi));
    }
}

// ---------------- RoPE in-place on q and k ----------------
__global__ __launch_bounds__(256) void rope_k(float* __restrict__ q, float* __restrict__ k) {
    int idx = blockIdx.x * 256 + threadIdx.x;
    int j  = idx & 127;
    int h  = (idx >> 7) & 7;
    int bt = idx >> 10;
    int pos = bt & (TLEN - 1);
    float inv = exp2f(-(float)j * (13.2877123795494f / 128.0f));
    float ph = (float)pos * inv;
    float s, c;
    sincosf(ph, &s, &c);
    size_t base = (size_t)bt * NQK + h * DKh + j;
    float x1 = q[base], x2 = q[base + 128];
    q[base]       = x1 * c - x2 * s;
    q[base + 128] = x2 * c + x1 * s;
    x1 = k[base]; x2 = k[base + 128];
    k[base]       = x1 * c - x2 * s;
    k[base + 128] = x2 * c + x1 * s;
}

// ---------------- Retention: per (b,h,i-tile of 32 rows), full DV=512 ----------------
#define RET_SMEM_BYTES ((2 * 32 * 260 + 32 * 512 + 32 * 33) * 4)

__global__ __launch_bounds__(256) void retention_k(const float* __restrict__ Q,
                                                   const float* __restrict__ Kt,
                                                   const float* __restrict__ V,
                                                   float* __restrict__ O) {
    extern __shared__ float sm[];
    float* Qs = sm;
    float* Ks = Qs + 32 * 260;
    float* Vs = Ks + 32 * 260;
    float* Ss = Vs + 32 * 512;

    const int t  = threadIdx.x;
    const int it = blockIdx.x;
    const int h  = blockIdx.y;
    const int b  = blockIdx.z;
    const int i0 = it * 32;
    const float scale = 0.0625f;
    const float gamma = 1.0f - exp2f(-5.0f - (float)h);
    const float l2g   = log2f(gamma);

    {
        const float* Qg = Q + ((size_t)(b * TLEN + i0)) * NQK + h * DKh;
#pragma unroll
        for (int u = 0; u < 8; u++) {
            int idx = t + u * 256;
            int row = idx >> 6, c4 = idx & 63;
            *(float4*)(Qs + row * 260 + c4 * 4) =
                *(const float4*)(Qg + (size_t)row * NQK + c4 * 4);
        }
    }

    const int tx = t & 31, ty = t >> 5;
    const int r_s = t & 31, jw = t >> 5;
    float4 acc[4][4];
#pragma unroll
    for (int rr = 0; rr < 4; rr++)
#pragma unroll
        for (int cb = 0; cb < 4; cb++) acc[rr][cb] = make_float4(0.f, 0.f, 0.f, 0.f);

    for (int jt = 0; jt <= it; jt++) {
        __syncthreads();
        const int j0 = jt * 32;
        const float* Kg = Kt + ((size_t)(b * TLEN + j0)) * NQK + h * DKh;
#pragma unroll
        for (int u = 0; u < 8; u++) {
            int idx = t + u * 256;
            int row = idx >> 6, c4 = idx & 63;
            *(float4*)(Ks + row * 260 + c4 * 4) =
                *(const float4*)(Kg + (size_t)row * NQK + c4 * 4);
        }
        const float* Vg = V + ((size_t)(b * TLEN + j0)) * NVG + h * DVh;
#pragma unroll
        for (int u = 0; u < 16; u++) {
            int idx = t + u * 256;
            int row = idx >> 7, c4 = idx & 127;
            *(float4*)(Vs + row * 512 + c4 * 4) =
                *(const float4*)(Vg + (size_t)row * NVG + c4 * 4);
        }
        __syncthreads();

        float s0 = 0.f, s1 = 0.f, s2 = 0.f, s3 = 0.f;
        {
            const float4* q4 = (const float4*)(Qs + r_s * 260);
#pragma unroll 4
            for (int d4 = 0; d4 < 64; d4++) {
                float4 qv = q4[d4];
                float4 k0v = *(const float4*)(Ks + (jw * 4 + 0) * 260 + d4 * 4);
                float4 k1v = *(const float4*)(Ks + (jw * 4 + 1) * 260 + d4 * 4);
                float4 k2v = *(const float4*)(Ks + (jw * 4 + 2) * 260 + d4 * 4);
                float4 k3v = *(const float4*)(Ks + (jw * 4 + 3) * 260 + d4 * 4);
                s0 += qv.x * k0v.x + qv.y * k0v.y + qv.z * k0v.z + qv.w * k0v.w;
                s1 += qv.x * k1v.x + qv.y * k1v.y + qv.z * k1v.z + qv.w * k1v.w;
                s2 += qv.x * k2v.x + qv.y * k2v.y + qv.z * k2v.z + qv.w * k2v.w;
                s3 += qv.x * k3v.x + qv.y * k3v.y + qv.z * k3v.z + qv.w * k3v.w;
            }
        }
        {
            float sv[4] = {s0, s1, s2, s3};
#pragma unroll
            for (int u = 0; u < 4; u++) {
                int j = jw * 4 + u;
                float diff = (float)(i0 + r_s - (j0 + j));
                float w = (jt == it && j > r_s) ? 0.f : scale * exp2f(l2g * diff);
                Ss[r_s * 33 + j] = sv[u] * w;
            }
        }
        __syncthreads();

#pragma unroll 4
        for (int j = 0; j < 32; j++) {
            float sr0 = Ss[(ty * 4 + 0) * 33 + j];
            float sr1 = Ss[(ty * 4 + 1) * 33 + j];
            float sr2 = Ss[(ty * 4 + 2) * 33 + j];
            float sr3 = Ss[(ty * 4 + 3) * 33 + j];
#pragma unroll
            for (int cb = 0; cb < 4; cb++) {
                float4 vv = *(const float4*)(Vs + j * 512 + tx * 4 + cb * 128);
                acc[0][cb].x += sr0 * vv.x; acc[0][cb].y += sr0 * vv.y;
                acc[0][cb].z += sr0 * vv.z; acc[0][cb].w += sr0 * vv.w;
                acc[1][cb].x += sr1 * vv.x; acc[1][cb].y += sr1 * vv.y;
                acc[1][cb].z += sr1 * vv.z; acc[1][cb].w += sr1 * vv.w;
                acc[2][cb].x += sr2 * vv.x; acc[2][cb].y += sr2 * vv.y;
                acc[2][cb].z += sr2 * vv.z; acc[2][cb].w += sr2 * vv.w;
                acc[3][cb].x += sr3 * vv.x; acc[3][cb].y += sr3 * vv.y;
                acc[3][cb].z += sr3 * vv.z; acc[3][cb].w += sr3 * vv.w;
            }
        }
    }

    float* Og = O + ((size_t)(b * TLEN + i0 + ty * 4)) * NVG + h * DVh;
#pragma unroll
    for (int rr = 0; rr < 4; rr++)
#pragma unroll
        for (int cb = 0; cb < 4; cb++)
            *(float4*)(Og + (size_t)rr * NVG + tx * 4 + cb * 128) = acc[rr][cb];
}

// ---------------- RMS norm (over DV) + SiLU gate, in-place on o ----------------
__global__ __launch_bounds__(256) void rmsgate_k(float* __restrict__ o,
                                                 const float* __restrict__ g,
                                                 const float* __restrict__ w) {
    int warp = (blockIdx.x * 256 + threadIdx.x) >> 5;
    int lane = threadIdx.x & 31;
    size_t base = (size_t)(warp >> 3) * NVG + (size_t)(warp & 7) * DVh;
    float ov[16];
    float ss = 0.f;
#pragma unroll
    for (int u = 0; u < 16; u++) {
        ov[u] = o[base + lane + u * 32];
        ss += ov[u] * ov[u];
    }
#pragma unroll
    for (int off = 16; off; off >>= 1) ss += __shfl_xor_sync(0xFFFFFFFFu, ss, off);
    float r = rsqrtf(ss * (1.0f / 512.0f) + 1e-5f);
#pragma unroll
    for (int u = 0; u < 16; u++) {
        int c = lane + u * 32;
        float gv = g[base + c];
        float gate = gv / (1.f + expf(-gv));
        o[base + c] = ov[u] * r * w[c] * gate;
    }
}

extern "C" void kernel_launch(void* const* d_in, const int* in_sizes, int n_in,
                              void* d_out, int out_size) {
    const float* X   = (const float*)d_in[0];
    const float* Wq  = (const float*)d_in[1];
    const float* Wk  = (const float*)d_in[2];
    const float* Wv  = (const float*)d_in[3];
    const float* Wg  = (const float*)d_in[4];
    const float* Wo  = (const float*)d_in[5];
    const float* gnw = (const float*)d_in[6];
    float* out = (float*)d_out;

    unsigned char* pool = nullptr;
    cudaGetSymbolAddress((void**)&pool, g_pool);

    float* dq  = (float*)pool;
    float* dk  = dq  + 8388608;
    float* dv  = dk  + 8388608;
    float* dg  = dv  + 16777216;
    float* dro = dg  + 16777216;
    __nv_bfloat16* bf = (__nv_bfloat16*)(dro + 16777216);
    __nv_bfloat16* Xh   = bf;             __nv_bfloat16* Xl   = Xh   + 8388608;
    __nv_bfloat16* WqTh = Xl   + 8388608; __nv_bfloat16* WqTl = WqTh + 4194304;
    __nv_bfloat16* WkTh = WqTl + 4194304; __nv_bfloat16* WkTl = WkTh + 4194304;
    __nv_bfloat16* WvTh = WkTl + 4194304; __nv_bfloat16* WvTl = WvTh + 8388608;
    __nv_bfloat16* WgTh = WvTl + 8388608; __nv_bfloat16* WgTl = WgTh + 8388608;
    __nv_bfloat16* WoTh = WgTl + 8388608; __nv_bfloat16* WoTl = WoTh + 8388608;
    __nv_bfloat16* droH = WoTl + 8388608; __nv_bfloat16* droL = droH + 16777216;

    cudaFuncSetAttribute(gemm_mma, cudaFuncAttributeMaxDynamicSharedMemorySize, GEMM_SMEM);
    cudaFuncSetAttribute(retention_k, cudaFuncAttributeMaxDynamicSharedMemorySize,
                         RET_SMEM_BYTES);

    dim3 thr(256);
    // splits
    split_k<<<8388608 / 1024, thr>>>(X, Xh, Xl);
    splitT_k<<<dim3(NQK / 32, HID / 32), thr>>>(Wq, WqTh, WqTl, HID, NQK);
    splitT_k<<<dim3(NQK / 32, HID / 32), thr>>>(Wk, WkTh, WkTl, HID, NQK);
    splitT_k<<<dim3(NVG / 32, HID / 32), thr>>>(Wv, WvTh, WvTl, HID, NVG);
    splitT_k<<<dim3(NVG / 32, HID / 32), thr>>>(Wg, WgTh, WgTl, HID, NVG);
    splitT_k<<<dim3(HID / 32, NVG / 32), thr>>>(Wo, WoTh, WoTl, NVG, HID);

    // projections (HMMA tensor cores)
    gemm_mma<<<dim3(NQK / 128, MTOT / 128), thr, GEMM_SMEM>>>(Xh, Xl, WqTh, WqTl, dq,
                                                              MTOT, NQK, HID);
    gemm_mma<<<dim3(NQK / 128, MTOT / 128), thr, GEMM_SMEM>>>(Xh, Xl, WkTh, WkTl, dk,
                                                              MTOT, NQK, HID);
    gemm_mma<<<dim3(NVG / 128, MTOT / 128), thr, GEMM_SMEM>>>(Xh, Xl, WvTh, WvTl, dv,
                                                              MTOT, NVG, HID);
    gemm_mma<<<dim3(NVG / 128, MTOT / 128), thr, GEMM_SMEM>>>(Xh, Xl, WgTh, WgTl, dg,
                                                              MTOT, NVG, HID);

    rope_k<<<16384, 256>>>(dq, dk);

    retention_k<<<dim3(TLEN / 32, HQ, 2), thr, RET_SMEM_BYTES>>>(dq, dk, dv, dro);

    rmsgate_k<<<4096, 256>>>(dro, dg, gnw);

    split_k<<<16777216 / 1024, thr>>>(dro, droH, droL);
    gemm_mma<<<dim3(HID / 128, MTOT / 128), thr, GEMM_SMEM>>>(droH, droL, WoTh, WoTl, out,
                                                              MTOT, HID, NVG);
}

// round 6
// speedup vs baseline: 2.1561x; 1.3382x over previous
#include <cuda_runtime.h>
#include <cuda_bf16.h>
#include <stdint.h>
#include <cstdint>
#include <math.h>

#define MTOT 4096      // B*T
#define TLEN 2048
#define HQ   8
#define DKh  256
#define DVh  512
#define HID  2048
#define NQK  2048      // H*DK
#define NVG  4096      // H*DV

// ---------------- big device pool (allocation-free scratch) ----------------
// fp32 268,435,456 B + bf16 (117,440,512 + 67,108,864 elems)*2 B = 637,534,208 B
__device__ __align__(1024) unsigned char g_pool[637534208];

__device__ __forceinline__ uint32_t smem_to_u32(const void* p) {
    uint32_t a;
    asm("{ .reg .u64 t; cvta.to.shared.u64 t, %1; cvt.u32.u64 %0, t; }"
        : "=r"(a) : "l"(p));
    return a;
}
#define SMEM_SWIZZLE_128B(byte_offset) \
    ((byte_offset) ^ (((byte_offset) >> 3) & 0x70))
// row-XOR swizzle: rotate 16B chunks within each 128B group by row (conflict-free
// for both row-linear writes and 8-row column (trans) ldmatrix reads)
#define ROWSWZ(row, c2) ((c2) ^ (((row) & 7) << 4))

// -------- mma.sync / ldmatrix helpers (generic sm_80+ PTX, sm_103-safe) --------
__device__ __forceinline__ void ldmx4(uint32_t& r0, uint32_t& r1, uint32_t& r2,
                                      uint32_t& r3, uint32_t addr) {
    asm volatile("ldmatrix.sync.aligned.m8n8.x4.shared.b16 {%0,%1,%2,%3}, [%4];"
                 : "=r"(r0), "=r"(r1), "=r"(r2), "=r"(r3) : "r"(addr));
}
__device__ __forceinline__ void ldmx2(uint32_t& r0, uint32_t& r1, uint32_t addr) {
    asm volatile("ldmatrix.sync.aligned.m8n8.x2.shared.b16 {%0,%1}, [%2];"
                 : "=r"(r0), "=r"(r1) : "r"(addr));
}
__device__ __forceinline__ void ldmx2t(uint32_t& r0, uint32_t& r1, uint32_t addr) {
    asm volatile("ldmatrix.sync.aligned.m8n8.x2.trans.shared.b16 {%0,%1}, [%2];"
                 : "=r"(r0), "=r"(r1) : "r"(addr));
}
__device__ __forceinline__ void mma16816(float& c0, float& c1, float& c2, float& c3,
                                         uint32_t a0, uint32_t a1, uint32_t a2,
                                         uint32_t a3, uint32_t b0, uint32_t b1) {
    asm volatile(
        "mma.sync.aligned.m16n8k16.row.col.f32.bf16.bf16.f32 "
        "{%0,%1,%2,%3}, {%4,%5,%6,%7}, {%8,%9}, {%0,%1,%2,%3};"
        : "+f"(c0), "+f"(c1), "+f"(c2), "+f"(c3)
        : "r"(a0), "r"(a1), "r"(a2), "r"(a3), "r"(b0), "r"(b1));
}

// ================= HMMA GEMM: C[M,N] = A[M,K] @ B[K,N] =================
#define GEMM_TILE_BYTES 16384
#define GEMM_STAGE_BYTES (4 * GEMM_TILE_BYTES)
#define GEMM_SMEM (2 * GEMM_STAGE_BYTES)

__global__ __launch_bounds__(256, 1) void gemm_mma(
    const __nv_bfloat16* __restrict__ Ah, const __nv_bfloat16* __restrict__ Al,
    const __nv_bfloat16* __restrict__ Bh, const __nv_bfloat16* __restrict__ Bl,
    float* __restrict__ C, int M, int N, int K) {
    extern __shared__ char smem[];
    const uint32_t sb = smem_to_u32(smem);
    const int tid  = threadIdx.x;
    const int wid  = tid >> 5, lane = tid & 31;
    const int wm   = (wid & 1) * 64;
    const int wn   = (wid >> 1) * 32;

    const size_t aRow = (size_t)blockIdx.y * 128;
    const size_t bRow = (size_t)blockIdx.x * 128;
    const __nv_bfloat16* srcs[4] = {Ah + aRow * K, Al + aRow * K,
                                    Bh + bRow * K, Bl + bRow * K};
    const int KC = K >> 6;

    const int a_r = lane & 15;
    const int a_k = (lane >> 4) * 8;
    const int b_r = lane & 7;
    const int b_k = ((lane >> 3) & 1) * 8;

    float acc[4][4][4];
#pragma unroll
    for (int mt = 0; mt < 4; mt++)
#pragma unroll
        for (int nt = 0; nt < 4; nt++)
#pragma unroll
            for (int e = 0; e < 4; e++) acc[mt][nt][e] = 0.f;

    {
        char* stage = smem;
#pragma unroll
        for (int t4 = 0; t4 < 4; t4++) {
            const __nv_bfloat16* src = srcs[t4];
            char* dst = stage + t4 * GEMM_TILE_BYTES;
#pragma unroll
            for (int u = 0; u < 4; u++) {
                int idx = tid + u * 256;
                int r = idx >> 3, c = idx & 7;
                uint4 v = *(const uint4*)(src + (size_t)r * K + c * 8);
                *(uint4*)(dst + SMEM_SWIZZLE_128B(r * 128 + c * 16)) = v;
            }
        }
    }
    __syncthreads();

    for (int kc = 0; kc < KC; kc++) {
        if (kc + 1 < KC) {
            char* stage = smem + ((kc + 1) & 1) * GEMM_STAGE_BYTES;
#pragma unroll
            for (int t4 = 0; t4 < 4; t4++) {
                const __nv_bfloat16* src = srcs[t4] + (kc + 1) * 64;
                char* dst = stage + t4 * GEMM_TILE_BYTES;
#pragma unroll
                for (int u = 0; u < 4; u++) {
                    int idx = tid + u * 256;
                    int r = idx >> 3, c = idx & 7;
                    uint4 v = *(const uint4*)(src + (size_t)r * K + c * 8);
                    *(uint4*)(dst + SMEM_SWIZZLE_128B(r * 128 + c * 16)) = v;
                }
            }
        }

        const uint32_t base = sb + (kc & 1) * GEMM_STAGE_BYTES;
        const uint32_t tAh = base;
        const uint32_t tAl = base + GEMM_TILE_BYTES;
        const uint32_t tBh = base + 2 * GEMM_TILE_BYTES;
        const uint32_t tBl = base + 3 * GEMM_TILE_BYTES;
#pragma unroll
        for (int ks = 0; ks < 4; ks++) {
            const int k0 = ks * 16;
            uint32_t bh[4][2], bl[4][2];
#pragma unroll
            for (int nt = 0; nt < 4; nt++) {
                int row = wn + nt * 8 + b_r;
                uint32_t off = SMEM_SWIZZLE_128B(row * 128 + (k0 + b_k) * 2);
                ldmx2(bh[nt][0], bh[nt][1], tBh + off);
                ldmx2(bl[nt][0], bl[nt][1], tBl + off);
            }
#pragma unroll
            for (int mt = 0; mt < 4; mt++) {
                int rowA = wm + mt * 16 + a_r;
                uint32_t offA = SMEM_SWIZZLE_128B(rowA * 128 + (k0 + a_k) * 2);
                uint32_t a0, a1, a2, a3;
                ldmx4(a0, a1, a2, a3, tAh + offA);
#pragma unroll
                for (int nt = 0; nt < 4; nt++)
                    mma16816(acc[mt][nt][0], acc[mt][nt][1], acc[mt][nt][2],
                             acc[mt][nt][3], a0, a1, a2, a3, bh[nt][0], bh[nt][1]);
#pragma unroll
                for (int nt = 0; nt < 4; nt++)
                    mma16816(acc[mt][nt][0], acc[mt][nt][1], acc[mt][nt][2],
                             acc[mt][nt][3], a0, a1, a2, a3, bl[nt][0], bl[nt][1]);
                uint32_t l0, l1, l2, l3;
                ldmx4(l0, l1, l2, l3, tAl + offA);
#pragma unroll
                for (int nt = 0; nt < 4; nt++)
                    mma16816(acc[mt][nt][0], acc[mt][nt][1], acc[mt][nt][2],
                             acc[mt][nt][3], l0, l1, l2, l3, bh[nt][0], bh[nt][1]);
            }
        }
        __syncthreads();
    }

#pragma unroll
    for (int mt = 0; mt < 4; mt++) {
        size_t m0 = aRow + wm + mt * 16 + (lane >> 2);
#pragma unroll
        for (int nt = 0; nt < 4; nt++) {
            size_t n0 = bRow + wn + nt * 8 + (lane & 3) * 2;
            *(float2*)(C + m0 * N + n0)       = make_float2(acc[mt][nt][0], acc[mt][nt][1]);
            *(float2*)(C + (m0 + 8) * N + n0) = make_float2(acc[mt][nt][2], acc[mt][nt][3]);
        }
    }
}

// ------------- fp32 -> bf16 hi/lo split -------------
__global__ __launch_bounds__(256) void split_k(const float* __restrict__ in,
                                               __nv_bfloat16* __restrict__ h,
                                               __nv_bfloat16* __restrict__ l) {
    int i = (blockIdx.x * 256 + threadIdx.x) * 4;
    float4 v = *(const float4*)(in + i);
    float x;
    __nv_bfloat16 hv[4], lv[4];
    x = v.x; hv[0] = __float2bfloat16(x); lv[0] = __float2bfloat16(x - __bfloat162float(hv[0]));
    x = v.y; hv[1] = __float2bfloat16(x); lv[1] = __float2bfloat16(x - __bfloat162float(hv[1]));
    x = v.z; hv[2] = __float2bfloat16(x); lv[2] = __float2bfloat16(x - __bfloat162float(hv[2]));
    x = v.w; hv[3] = __float2bfloat16(x); lv[3] = __float2bfloat16(x - __bfloat162float(hv[3]));
    *(uint2*)(h + i) = *(uint2*)hv;
    *(uint2*)(l + i) = *(uint2*)lv;
}

// ------------- fp32 [K,N] -> bf16 hi/lo transposed [N,K] -------------
__global__ __launch_bounds__(256) void splitT_k(const float* __restrict__ in,
                                                __nv_bfloat16* __restrict__ hT,
                                                __nv_bfloat16* __restrict__ lT,
                                                int K, int N) {
    __shared__ float ts[32][33];
    int n0 = blockIdx.x * 32, k0 = blockIdx.y * 32;
    int tx = threadIdx.x & 31, ty = threadIdx.x >> 5;
#pragma unroll
    for (int r = 0; r < 4; r++)
        ts[ty + r * 8][tx] = in[(size_t)(k0 + ty + r * 8) * N + n0 + tx];
    __syncthreads();
#pragma unroll
    for (int r = 0; r < 4; r++) {
        int n = n0 + ty + r * 8, kk = k0 + tx;
        float x = ts[tx][ty + r * 8];
        __nv_bfloat16 hi = __float2bfloat16(x);
        hT[(size_t)n * K + kk] = hi;
        lT[(size_t)n * K + kk] = __float2bfloat16(x - __bfloat162float(hi));
    }
}

// ---------------- RoPE in-place on q and k ----------------
__global__ __launch_bounds__(256) void rope_k(float* __restrict__ q, float* __restrict__ k) {
    int idx = blockIdx.x * 256 + threadIdx.x;
    int j  = idx & 127;
    int h  = (idx >> 7) & 7;
    int bt = idx >> 10;
    int pos = bt & (TLEN - 1);
    float inv = exp2f(-(float)j * (13.2877123795494f / 128.0f));
    float ph = (float)pos * inv;
    float s, c;
    sincosf(ph, &s, &c);
    size_t base = (size_t)bt * NQK + h * DKh + j;
    float x1 = q[base], x2 = q[base + 128];
    q[base]       = x1 * c - x2 * s;
    q[base + 128] = x2 * c + x1 * s;
    x1 = k[base]; x2 = k[base + 128];
    k[base]       = x1 * c - x2 * s;
    k[base + 128] = x2 * c + x1 * s;
}

// ============ Tensor-core retention: i-tile 64, j-tile 32, 512 thr ============
// smem bytes: Qh 0(32K) Ql 32K Kh 64K(16K) Kl 80K Vh 96K(32K) Vl 128K
//             Ssh 160K(8K) Ssl 168K  -> total 176K
#define RQh  0
#define RQl  32768
#define RKh  65536
#define RKl  81920
#define RVh  98304
#define RVl  131072
#define RSh  163840
#define RSl  172032
#define RET_TC_SMEM 180224

__global__ __launch_bounds__(512, 1) void retention_tc(
    const __nv_bfloat16* __restrict__ Qh, const __nv_bfloat16* __restrict__ Ql,
    const __nv_bfloat16* __restrict__ Kh, const __nv_bfloat16* __restrict__ Kl,
    const __nv_bfloat16* __restrict__ Vh, const __nv_bfloat16* __restrict__ Vl,
    float* __restrict__ O) {
    extern __shared__ char smem[];
    const uint32_t sb = smem_to_u32(smem);
    const int tid  = threadIdx.x;
    const int wid  = tid >> 5, lane = tid & 31;
    const int wm   = wid & 3;         // M quarter (16 rows)
    const int wn   = wid >> 2;        // 0..3

    const int it = 31 - blockIdx.x;   // largest-first
    const int h  = blockIdx.y;
    const int b  = blockIdx.z;
    const int i0 = it * 64;
    const float scale = 0.0625f;
    const float gamma = 1.0f - exp2f(-5.0f - (float)h);
    const float l2g   = log2f(gamma);

    // ---- load Q tile (hi/lo), 64 rows x 512B, row-XOR swizzle ----
    {
        const size_t gbase = (size_t)(b * TLEN + i0) * NQK + h * DKh;
#pragma unroll
        for (int u = 0; u < 4; u++) {
            int idx = tid + u * 512;            // 0..2047 16B-chunks
            int r = idx >> 5, c16 = (idx & 31) * 16;
            uint32_t so = r * 512 + ROWSWZ(r, c16);
            size_t ga = gbase + (size_t)r * NQK + (c16 >> 1);
            *(uint4*)(smem + RQh + so) = *(const uint4*)(Qh + ga);
            *(uint4*)(smem + RQl + so) = *(const uint4*)(Ql + ga);
        }
    }

    float accO[16][4];
#pragma unroll
    for (int nf = 0; nf < 16; nf++)
#pragma unroll
        for (int e = 0; e < 4; e++) accO[nf][e] = 0.f;

    // skip j-tiles whose decay weight is entirely < 2^-45
    int jt0 = 0;
    {
        float Dh = -45.0f / l2g;                 // max useful diff
        int jlow = i0 - 31 - (int)Dh;
        if (jlow > 0) jt0 = jlow >> 5;
    }
    const int jtmax = it * 2 + 1;

    for (int jt = jt0; jt <= jtmax; jt++) {
        __syncthreads();                          // protect prev K/V/S reads
        const int j0 = jt * 32;
        // ---- load K (32x512B) + V (32x1024B) hi/lo ----
        {
            const size_t kb = (size_t)(b * TLEN + j0) * NQK + h * DKh;
#pragma unroll
            for (int u = 0; u < 2; u++) {
                int idx = tid + u * 512;          // 0..1023
                int r = idx >> 5, c16 = (idx & 31) * 16;
                uint32_t so = r * 512 + ROWSWZ(r, c16);
                size_t ga = kb + (size_t)r * NQK + (c16 >> 1);
                *(uint4*)(smem + RKh + so) = *(const uint4*)(Kh + ga);
                *(uint4*)(smem + RKl + so) = *(const uint4*)(Kl + ga);
            }
            const size_t vb = (size_t)(b * TLEN + j0) * NVG + h * DVh;
#pragma unroll
            for (int u = 0; u < 4; u++) {
                int idx = tid + u * 512;          // 0..2047
                int r = idx >> 6, c16 = (idx & 63) * 16;
                uint32_t so = r * 1024 + ROWSWZ(r, c16);
                size_t ga = vb + (size_t)r * NVG + (c16 >> 1);
                *(uint4*)(smem + RVh + so) = *(const uint4*)(Vh + ga);
                *(uint4*)(smem + RVl + so) = *(const uint4*)(Vl + ga);
            }
        }
        __syncthreads();

        // ---- S = Q K^T (3-term) ----
        float accS[4] = {0.f, 0.f, 0.f, 0.f};
        {
            const int ar = wm * 16 + (lane & 15);
            const int akb = (lane >> 4) * 16;
            const int br = wn * 8 + (lane & 7);
            const int bkb = ((lane >> 3) & 1) * 16;
            const uint32_t qhb = sb + RQh, qlb = sb + RQl;
            const uint32_t khb = sb + RKh, klb = sb + RKl;
#pragma unroll
            for (int ks = 0; ks < 16; ks++) {
                uint32_t aoff = ar * 512 + ROWSWZ(ar, ks * 32 + akb);
                uint32_t boff = br * 512 + ROWSWZ(br, ks * 32 + bkb);
                uint32_t a0, a1, a2, a3, l0, l1, l2, l3, b0, b1, c0, c1;
                ldmx4(a0, a1, a2, a3, qhb + aoff);
                ldmx2(b0, b1, khb + boff);
                mma16816(accS[0], accS[1], accS[2], accS[3], a0, a1, a2, a3, b0, b1);
                ldmx2(c0, c1, klb + boff);
                mma16816(accS[0], accS[1], accS[2], accS[3], a0, a1, a2, a3, c0, c1);
                ldmx4(l0, l1, l2, l3, qlb + aoff);
                mma16816(accS[0], accS[1], accS[2], accS[3], l0, l1, l2, l3, b0, b1);
            }
        }
        // ---- decay + mask + split, store to Ssh/Ssl ----
        {
            const int il = wm * 16 + (lane >> 2);
            const int jl = wn * 8 + (lane & 3) * 2;
#pragma unroll
            for (int half = 0; half < 2; half++) {
                int r = il + half * 8;
                int d0 = (i0 + r) - (j0 + jl);
                int d1 = d0 - 1;
                float w0 = (d0 >= 0) ? scale * exp2f(l2g * (float)d0) : 0.f;
                float w1 = (d1 >= 0) ? scale * exp2f(l2g * (float)d1) : 0.f;
                float s0 = accS[half * 2 + 0] * w0;
                float s1 = accS[half * 2 + 1] * w1;
                __nv_bfloat16 h0 = __float2bfloat16(s0);
                __nv_bfloat16 h1 = __float2bfloat16(s1);
                __nv_bfloat16 e0 = __float2bfloat16(s0 - __bfloat162float(h0));
                __nv_bfloat16 e1 = __float2bfloat16(s1 - __bfloat162float(h1));
                uint32_t hp = ((uint32_t)*(uint16_t*)&h1 << 16) | *(uint16_t*)&h0;
                uint32_t lp = ((uint32_t)*(uint16_t*)&e1 << 16) | *(uint16_t*)&e0;
                uint32_t so = r * 128 + ROWSWZ(r, jl * 2);
                *(uint32_t*)(smem + RSh + so) = hp;
                *(uint32_t*)(smem + RSl + so) = lp;
            }
        }
        __syncthreads();

        // ---- O += S V (3-term, V via trans ldmatrix) ----
        {
            const int ar = wm * 16 + (lane & 15);
            const int akb = (lane >> 4) * 16;
            const uint32_t shb = sb + RSh, slb = sb + RSl;
            const uint32_t vhb = sb + RVh, vlb = sb + RVl;
#pragma unroll
            for (int ks2 = 0; ks2 < 2; ks2++) {
                uint32_t aoff = ar * 128 + ROWSWZ(ar, ks2 * 32 + akb);
                uint32_t s0, s1, s2, s3, t0, t1, t2, t3;
                ldmx4(s0, s1, s2, s3, shb + aoff);
                ldmx4(t0, t1, t2, t3, slb + aoff);
                const int vr = ks2 * 16 + (lane & 15);
#pragma unroll
                for (int nf = 0; nf < 16; nf++) {
                    uint32_t voff = vr * 1024 + ROWSWZ(vr, (wn * 128 + nf * 8) * 2);
                    uint32_t v0, v1, u0, u1;
                    ldmx2t(v0, v1, vhb + voff);
                    mma16816(accO[nf][0], accO[nf][1], accO[nf][2], accO[nf][3],
                             s0, s1, s2, s3, v0, v1);
                    ldmx2t(u0, u1, vlb + voff);
                    mma16816(accO[nf][0], accO[nf][1], accO[nf][2], accO[nf][3],
                             s0, s1, s2, s3, u0, u1);
                    mma16816(accO[nf][0], accO[nf][1], accO[nf][2], accO[nf][3],
                             t0, t1, t2, t3, v0, v1);
                }
            }
        }
    }

    // ---- write O tile ----
    {
        const int il = wm * 16 + (lane >> 2);
        size_t r0 = (size_t)(b * TLEN + i0 + il);
#pragma unroll
        for (int nf = 0; nf < 16; nf++) {
            size_t col = h * DVh + wn * 128 + nf * 8 + (lane & 3) * 2;
            *(float2*)(O + r0 * NVG + col)       = make_float2(accO[nf][0], accO[nf][1]);
            *(float2*)(O + (r0 + 8) * NVG + col) = make_float2(accO[nf][2], accO[nf][3]);
        }
    }
}

// ---------------- RMS norm (over DV) + SiLU gate, in-place on o ----------------
__global__ __launch_bounds__(256) void rmsgate_k(float* __restrict__ o,
                                                 const float* __restrict__ g,
                                                 const float* __restrict__ w) {
    int warp = (blockIdx.x * 256 + threadIdx.x) >> 5;
    int lane = threadIdx.x & 31;
    size_t base = (size_t)(warp >> 3) * NVG + (size_t)(warp & 7) * DVh;
    float ov[16];
    float ss = 0.f;
#pragma unroll
    for (int u = 0; u < 16; u++) {
        ov[u] = o[base + lane + u * 32];
        ss += ov[u] * ov[u];
    }
#pragma unroll
    for (int off = 16; off; off >>= 1) ss += __shfl_xor_sync(0xFFFFFFFFu, ss, off);
    float r = rsqrtf(ss * (1.0f / 512.0f) + 1e-5f);
#pragma unroll
    for (int u = 0; u < 16; u++) {
        int c = lane + u * 32;
        float gv = g[base + c];
        float gate = gv / (1.f + expf(-gv));
        o[base + c] = ov[u] * r * w[c] * gate;
    }
}

extern "C" void kernel_launch(void* const* d_in, const int* in_sizes, int n_in,
                              void* d_out, int out_size) {
    const float* X   = (const float*)d_in[0];
    const float* Wq  = (const float*)d_in[1];
    const float* Wk  = (const float*)d_in[2];
    const float* Wv  = (const float*)d_in[3];
    const float* Wg  = (const float*)d_in[4];
    const float* Wo  = (const float*)d_in[5];
    const float* gnw = (const float*)d_in[6];
    float* out = (float*)d_out;

    unsigned char* pool = nullptr;
    cudaGetSymbolAddress((void**)&pool, g_pool);

    float* dq  = (float*)pool;
    float* dk  = dq  + 8388608;
    float* dv  = dk  + 8388608;
    float* dg  = dv  + 16777216;
    float* dro = dg  + 16777216;
    __nv_bfloat16* bf = (__nv_bfloat16*)(dro + 16777216);
    __nv_bfloat16* Xh   = bf;             __nv_bfloat16* Xl   = Xh   + 8388608;
    __nv_bfloat16* WqTh = Xl   + 8388608; __nv_bfloat16* WqTl = WqTh + 4194304;
    __nv_bfloat16* WkTh = WqTl + 4194304; __nv_bfloat16* WkTl = WkTh + 4194304;
    __nv_bfloat16* WvTh = WkTl + 4194304; __nv_bfloat16* WvTl = WvTh + 8388608;
    __nv_bfloat16* WgTh = WvTl + 8388608; __nv_bfloat16* WgTl = WgTh + 8388608;
    __nv_bfloat16* WoTh = WgTl + 8388608; __nv_bfloat16* WoTl = WoTh + 8388608;
    __nv_bfloat16* droH = WoTl + 8388608; __nv_bfloat16* droL = droH + 16777216;
    __nv_bfloat16* qh   = droL + 16777216; __nv_bfloat16* ql = qh + 8388608;
    __nv_bfloat16* kh   = ql + 8388608;    __nv_bfloat16* kl = kh + 8388608;
    __nv_bfloat16* vh   = kl + 8388608;    __nv_bfloat16* vl = vh + 16777216;

    cudaFuncSetAttribute(gemm_mma, cudaFuncAttributeMaxDynamicSharedMemorySize, GEMM_SMEM);
    cudaFuncSetAttribute(retention_tc, cudaFuncAttributeMaxDynamicSharedMemorySize,
                         RET_TC_SMEM);

    dim3 thr(256);
    // splits
    split_k<<<8388608 / 1024, thr>>>(X, Xh, Xl);
    splitT_k<<<dim3(NQK / 32, HID / 32), thr>>>(Wq, WqTh, WqTl, HID, NQK);
    splitT_k<<<dim3(NQK / 32, HID / 32), thr>>>(Wk, WkTh, WkTl, HID, NQK);
    splitT_k<<<dim3(NVG / 32, HID / 32), thr>>>(Wv, WvTh, WvTl, HID, NVG);
    splitT_k<<<dim3(NVG / 32, HID / 32), thr>>>(Wg, WgTh, WgTl, HID, NVG);
    splitT_k<<<dim3(HID / 32, NVG / 32), thr>>>(Wo, WoTh, WoTl, NVG, HID);

    // projections (HMMA tensor cores)
    gemm_mma<<<dim3(NQK / 128, MTOT / 128), thr, GEMM_SMEM>>>(Xh, Xl, WqTh, WqTl, dq,
                                                              MTOT, NQK, HID);
    gemm_mma<<<dim3(NQK / 128, MTOT / 128), thr, GEMM_SMEM>>>(Xh, Xl, WkTh, WkTl, dk,
                                                              MTOT, NQK, HID);
    gemm_mma<<<dim3(NVG / 128, MTOT / 128), thr, GEMM_SMEM>>>(Xh, Xl, WvTh, WvTl, dv,
                                                              MTOT, NVG, HID);
    gemm_mma<<<dim3(NVG / 128, MTOT / 128), thr, GEMM_SMEM>>>(Xh, Xl, WgTh, WgTl, dg,
                                                              MTOT, NVG, HID);

    rope_k<<<16384, 256>>>(dq, dk);

    // split q/k/v to bf16 hi/lo for tensor-core retention
    split_k<<<8388608 / 1024, thr>>>(dq, qh, ql);
    split_k<<<8388608 / 1024, thr>>>(dk, kh, kl);
    split_k<<<16777216 / 1024, thr>>>(dv, vh, vl);

    retention_tc<<<dim3(32, HQ, 2), dim3(512), RET_TC_SMEM>>>(qh, ql, kh, kl, vh, vl, dro);

    rmsgate_k<<<4096, 256>>>(dro, dg, gnw);

    split_k<<<16777216 / 1024, thr>>>(dro, droH, droL);
    gemm_mma<<<dim3(HID / 128, MTOT / 128), thr, GEMM_SMEM>>>(droH, droL, WoTh, WoTl, out,
                                                              MTOT, HID, NVG);
}

// round 7
// speedup vs baseline: 2.8459x; 1.3200x over previous
#include <cuda_runtime.h>
#include <cuda_bf16.h>
#include <stdint.h>
#include <cstdint>
#include <math.h>

#define MTOT 4096      // B*T
#define TLEN 2048
#define HQ   8
#define DKh  256
#define DVh  512
#define HID  2048
#define NQK  2048      // H*DK
#define NVG  4096      // H*DV

__device__ __align__(1024) unsigned char g_pool[637534208];

__device__ __forceinline__ uint32_t smem_to_u32(const void* p) {
    uint32_t a;
    asm("{ .reg .u64 t; cvta.to.shared.u64 t, %1; cvt.u32.u64 %0, t; }"
        : "=r"(a) : "l"(p));
    return a;
}
#define SMEM_SWIZZLE_128B(byte_offset) \
    ((byte_offset) ^ (((byte_offset) >> 3) & 0x70))
#define ROWSWZ(row, c2) ((c2) ^ (((row) & 7) << 4))

#define CP_ASYNC16(dst_u32, gptr) \
    asm volatile("cp.async.cg.shared.global [%0], [%1], 16;" \
                 :: "r"(dst_u32), "l"(gptr))
#define CP_COMMIT() asm volatile("cp.async.commit_group;" ::: "memory")
#define CP_WAIT(n)  asm volatile("cp.async.wait_group %0;" :: "n"(n) : "memory")

// -------- mma.sync / ldmatrix helpers --------
__device__ __forceinline__ void ldmx4(uint32_t& r0, uint32_t& r1, uint32_t& r2,
                                      uint32_t& r3, uint32_t addr) {
    asm volatile("ldmatrix.sync.aligned.m8n8.x4.shared.b16 {%0,%1,%2,%3}, [%4];"
                 : "=r"(r0), "=r"(r1), "=r"(r2), "=r"(r3) : "r"(addr));
}
__device__ __forceinline__ void ldmx2(uint32_t& r0, uint32_t& r1, uint32_t addr) {
    asm volatile("ldmatrix.sync.aligned.m8n8.x2.shared.b16 {%0,%1}, [%2];"
                 : "=r"(r0), "=r"(r1) : "r"(addr));
}
__device__ __forceinline__ void ldmx2t(uint32_t& r0, uint32_t& r1, uint32_t addr) {
    asm volatile("ldmatrix.sync.aligned.m8n8.x2.trans.shared.b16 {%0,%1}, [%2];"
                 : "=r"(r0), "=r"(r1) : "r"(addr));
}
__device__ __forceinline__ void mma16816(float& c0, float& c1, float& c2, float& c3,
                                         uint32_t a0, uint32_t a1, uint32_t a2,
                                         uint32_t a3, uint32_t b0, uint32_t b1) {
    asm volatile(
        "mma.sync.aligned.m16n8k16.row.col.f32.bf16.bf16.f32 "
        "{%0,%1,%2,%3}, {%4,%5,%6,%7}, {%8,%9}, {%0,%1,%2,%3};"
        : "+f"(c0), "+f"(c1), "+f"(c2), "+f"(c3)
        : "r"(a0), "r"(a1), "r"(a2), "r"(a3), "r"(b0), "r"(b1));
}
__device__ __forceinline__ uint32_t pack_hi(float a, float b) {
    __nv_bfloat16 x = __float2bfloat16(a), y = __float2bfloat16(b);
    return ((uint32_t)*(uint16_t*)&y << 16) | *(uint16_t*)&x;
}
__device__ __forceinline__ uint32_t pack_lo(float a, float b) {
    __nv_bfloat16 x = __float2bfloat16(a), y = __float2bfloat16(b);
    float ra = a - __bfloat162float(x), rb = b - __bfloat162float(y);
    __nv_bfloat16 u = __float2bfloat16(ra), v = __float2bfloat16(rb);
    return ((uint32_t)*(uint16_t*)&v << 16) | *(uint16_t*)&u;
}

// ================= HMMA GEMM with cp.async 3-stage pipeline =================
#define GEMM_TILE_BYTES 16384
#define GEMM_STAGE_BYTES (4 * GEMM_TILE_BYTES)
#define GEMM_STAGES 3
#define GEMM_SMEM (GEMM_STAGES * GEMM_STAGE_BYTES)   // 196608

__device__ __forceinline__ void gemm_issue_stage(
    const __nv_bfloat16* s0, const __nv_bfloat16* s1,
    const __nv_bfloat16* s2, const __nv_bfloat16* s3,
    int kc, uint32_t stage_u32, int tid, int K) {
    const __nv_bfloat16* srcs[4] = {s0, s1, s2, s3};
#pragma unroll
    for (int t4 = 0; t4 < 4; t4++) {
        const __nv_bfloat16* src = srcs[t4] + (size_t)kc * 64;
        uint32_t dbase = stage_u32 + t4 * GEMM_TILE_BYTES;
#pragma unroll
        for (int u = 0; u < 4; u++) {
            int idx = tid + u * 256;
            int r = idx >> 3, c = idx & 7;
            uint32_t d = dbase + SMEM_SWIZZLE_128B(r * 128 + c * 16);
            CP_ASYNC16(d, src + (size_t)r * K + c * 8);
        }
    }
}

template <bool SPLIT>
__global__ __launch_bounds__(256, 1) void gemm_mma(
    const __nv_bfloat16* __restrict__ Ah, const __nv_bfloat16* __restrict__ Al,
    const __nv_bfloat16* __restrict__ Bh, const __nv_bfloat16* __restrict__ Bl,
    float* __restrict__ C, __nv_bfloat16* __restrict__ Ch,
    __nv_bfloat16* __restrict__ Cl, int M, int N, int K) {
    extern __shared__ char smem[];
    const uint32_t sb = smem_to_u32(smem);
    const int tid  = threadIdx.x;
    const int wid  = tid >> 5, lane = tid & 31;
    const int wm   = (wid & 1) * 64;
    const int wn   = (wid >> 1) * 32;

    const size_t aRow = (size_t)blockIdx.y * 128;
    const size_t bRow = (size_t)blockIdx.x * 128;
    const __nv_bfloat16* pAh = Ah + aRow * K;
    const __nv_bfloat16* pAl = Al + aRow * K;
    const __nv_bfloat16* pBh = Bh + bRow * K;
    const __nv_bfloat16* pBl = Bl + bRow * K;
    const int KC = K >> 6;

    const int a_r = lane & 15;
    const int a_k = (lane >> 4) * 8;
    const int b_r = lane & 7;
    const int b_k = ((lane >> 3) & 1) * 8;

    float acc[4][4][4];
#pragma unroll
    for (int mt = 0; mt < 4; mt++)
#pragma unroll
        for (int nt = 0; nt < 4; nt++)
#pragma unroll
            for (int e = 0; e < 4; e++) acc[mt][nt][e] = 0.f;

    // prologue: fill pipeline
#pragma unroll
    for (int s = 0; s < GEMM_STAGES; s++) {
        gemm_issue_stage(pAh, pAl, pBh, pBl, s, sb + s * GEMM_STAGE_BYTES, tid, K);
        CP_COMMIT();
    }

    for (int kc = 0; kc < KC; kc++) {
        CP_WAIT(GEMM_STAGES - 1);
        __syncthreads();

        const uint32_t base = sb + (kc % GEMM_STAGES) * GEMM_STAGE_BYTES;
        const uint32_t tAh = base;
        const uint32_t tAl = base + GEMM_TILE_BYTES;
        const uint32_t tBh = base + 2 * GEMM_TILE_BYTES;
        const uint32_t tBl = base + 3 * GEMM_TILE_BYTES;
#pragma unroll
        for (int ks = 0; ks < 4; ks++) {
            const int k0 = ks * 16;
            uint32_t bh[4][2], bl[4][2];
#pragma unroll
            for (int nt = 0; nt < 4; nt++) {
                int row = wn + nt * 8 + b_r;
                uint32_t off = SMEM_SWIZZLE_128B(row * 128 + (k0 + b_k) * 2);
                ldmx2(bh[nt][0], bh[nt][1], tBh + off);
                ldmx2(bl[nt][0], bl[nt][1], tBl + off);
            }
#pragma unroll
            for (int mt = 0; mt < 4; mt++) {
                int rowA = wm + mt * 16 + a_r;
                uint32_t offA = SMEM_SWIZZLE_128B(rowA * 128 + (k0 + a_k) * 2);
                uint32_t a0, a1, a2, a3;
                ldmx4(a0, a1, a2, a3, tAh + offA);
#pragma unroll
                for (int nt = 0; nt < 4; nt++)
                    mma16816(acc[mt][nt][0], acc[mt][nt][1], acc[mt][nt][2],
                             acc[mt][nt][3], a0, a1, a2, a3, bh[nt][0], bh[nt][1]);
#pragma unroll
                for (int nt = 0; nt < 4; nt++)
                    mma16816(acc[mt][nt][0], acc[mt][nt][1], acc[mt][nt][2],
                             acc[mt][nt][3], a0, a1, a2, a3, bl[nt][0], bl[nt][1]);
                uint32_t l0, l1, l2, l3;
                ldmx4(l0, l1, l2, l3, tAl + offA);
#pragma unroll
                for (int nt = 0; nt < 4; nt++)
                    mma16816(acc[mt][nt][0], acc[mt][nt][1], acc[mt][nt][2],
                             acc[mt][nt][3], l0, l1, l2, l3, bh[nt][0], bh[nt][1]);
            }
        }
        __syncthreads();   // all warps done reading before refill
        if (kc + GEMM_STAGES < KC) {
            gemm_issue_stage(pAh, pAl, pBh, pBl, kc + GEMM_STAGES,
                             sb + (kc % GEMM_STAGES) * GEMM_STAGE_BYTES, tid, K);
            CP_COMMIT();
        }
    }

    // epilogue
#pragma unroll
    for (int mt = 0; mt < 4; mt++) {
        size_t m0 = aRow + wm + mt * 16 + (lane >> 2);
#pragma unroll
        for (int nt = 0; nt < 4; nt++) {
            size_t n0 = bRow + wn + nt * 8 + (lane & 3) * 2;
            if (SPLIT) {
                *(uint32_t*)(Ch + m0 * N + n0) = pack_hi(acc[mt][nt][0], acc[mt][nt][1]);
                *(uint32_t*)(Cl + m0 * N + n0) = pack_lo(acc[mt][nt][0], acc[mt][nt][1]);
                *(uint32_t*)(Ch + (m0 + 8) * N + n0) = pack_hi(acc[mt][nt][2], acc[mt][nt][3]);
                *(uint32_t*)(Cl + (m0 + 8) * N + n0) = pack_lo(acc[mt][nt][2], acc[mt][nt][3]);
            } else {
                *(float2*)(C + m0 * N + n0)       = make_float2(acc[mt][nt][0], acc[mt][nt][1]);
                *(float2*)(C + (m0 + 8) * N + n0) = make_float2(acc[mt][nt][2], acc[mt][nt][3]);
            }
        }
    }
}

// ------------- fp32 -> bf16 hi/lo split -------------
__global__ __launch_bounds__(256) void split_k(const float* __restrict__ in,
                                               __nv_bfloat16* __restrict__ h,
                                               __nv_bfloat16* __restrict__ l) {
    int i = (blockIdx.x * 256 + threadIdx.x) * 4;
    float4 v = *(const float4*)(in + i);
    float x;
    __nv_bfloat16 hv[4], lv[4];
    x = v.x; hv[0] = __float2bfloat16(x); lv[0] = __float2bfloat16(x - __bfloat162float(hv[0]));
    x = v.y; hv[1] = __float2bfloat16(x); lv[1] = __float2bfloat16(x - __bfloat162float(hv[1]));
    x = v.z; hv[2] = __float2bfloat16(x); lv[2] = __float2bfloat16(x - __bfloat162float(hv[2]));
    x = v.w; hv[3] = __float2bfloat16(x); lv[3] = __float2bfloat16(x - __bfloat162float(hv[3]));
    *(uint2*)(h + i) = *(uint2*)hv;
    *(uint2*)(l + i) = *(uint2*)lv;
}

// ------------- fp32 [K,N] -> bf16 hi/lo transposed [N,K] -------------
__global__ __launch_bounds__(256) void splitT_k(const float* __restrict__ in,
                                                __nv_bfloat16* __restrict__ hT,
                                                __nv_bfloat16* __restrict__ lT,
                                                int K, int N) {
    __shared__ float ts[32][33];
    int n0 = blockIdx.x * 32, k0 = blockIdx.y * 32;
    int tx = threadIdx.x & 31, ty = threadIdx.x >> 5;
#pragma unroll
    for (int r = 0; r < 4; r++)
        ts[ty + r * 8][tx] = in[(size_t)(k0 + ty + r * 8) * N + n0 + tx];
    __syncthreads();
#pragma unroll
    for (int r = 0; r < 4; r++) {
        int n = n0 + ty + r * 8, kk = k0 + tx;
        float x = ts[tx][ty + r * 8];
        __nv_bfloat16 hi = __float2bfloat16(x);
        hT[(size_t)n * K + kk] = hi;
        lT[(size_t)n * K + kk] = __float2bfloat16(x - __bfloat162float(hi));
    }
}

// ---------------- fused RoPE + hi/lo split: fp32 q/k -> bf16 pairs ----------------
__global__ __launch_bounds__(256) void rope_split(const float* __restrict__ q,
                                                  const float* __restrict__ k,
                                                  __nv_bfloat16* __restrict__ qh,
                                                  __nv_bfloat16* __restrict__ ql,
                                                  __nv_bfloat16* __restrict__ kh,
                                                  __nv_bfloat16* __restrict__ kl) {
    int idx = blockIdx.x * 256 + threadIdx.x;
    int j  = idx & 127;
    int h  = (idx >> 7) & 7;
    int bt = idx >> 10;
    int pos = bt & (TLEN - 1);
    float inv = exp2f(-(float)j * (13.2877123795494f / 128.0f));
    float ph = (float)pos * inv;
    float s, c;
    sincosf(ph, &s, &c);
    size_t base = (size_t)bt * NQK + h * DKh + j;

    float x1 = q[base], x2 = q[base + 128];
    float o1 = x1 * c - x2 * s, o2 = x2 * c + x1 * s;
    __nv_bfloat16 hb = __float2bfloat16(o1);
    qh[base] = hb; ql[base] = __float2bfloat16(o1 - __bfloat162float(hb));
    hb = __float2bfloat16(o2);
    qh[base + 128] = hb; ql[base + 128] = __float2bfloat16(o2 - __bfloat162float(hb));

    x1 = k[base]; x2 = k[base + 128];
    o1 = x1 * c - x2 * s; o2 = x2 * c + x1 * s;
    hb = __float2bfloat16(o1);
    kh[base] = hb; kl[base] = __float2bfloat16(o1 - __bfloat162float(hb));
    hb = __float2bfloat16(o2);
    kh[base + 128] = hb; kl[base + 128] = __float2bfloat16(o2 - __bfloat162float(hb));
}

// ============ Tensor-core retention: i-tile 64, j-tile 32, 512 thr ============
#define RQh  0
#define RQl  32768
#define RKh  65536
#define RKl  81920
#define RVh  98304
#define RVl  131072
#define RSh  163840
#define RSl  172032
#define RET_TC_SMEM 180224

__global__ __launch_bounds__(512, 1) void retention_tc(
    const __nv_bfloat16* __restrict__ Qh, const __nv_bfloat16* __restrict__ Ql,
    const __nv_bfloat16* __restrict__ Kh, const __nv_bfloat16* __restrict__ Kl,
    const __nv_bfloat16* __restrict__ Vh, const __nv_bfloat16* __restrict__ Vl,
    float* __restrict__ O) {
    extern __shared__ char smem[];
    const uint32_t sb = smem_to_u32(smem);
    const int tid  = threadIdx.x;
    const int wid  = tid >> 5, lane = tid & 31;
    const int wm   = wid & 3;
    const int wn   = wid >> 2;

    const int it = 31 - blockIdx.x;
    const int h  = blockIdx.y;
    const int b  = blockIdx.z;
    const int i0 = it * 64;
    const float scale = 0.0625f;
    const float gamma = 1.0f - exp2f(-5.0f - (float)h);
    const float l2g   = log2f(gamma);

    {
        const size_t gbase = (size_t)(b * TLEN + i0) * NQK + h * DKh;
#pragma unroll
        for (int u = 0; u < 4; u++) {
            int idx = tid + u * 512;
            int r = idx >> 5, c16 = (idx & 31) * 16;
            uint32_t so = r * 512 + ROWSWZ(r, c16);
            size_t ga = gbase + (size_t)r * NQK + (c16 >> 1);
            CP_ASYNC16(sb + RQh + so, Qh + ga);
            CP_ASYNC16(sb + RQl + so, Ql + ga);
        }
        CP_COMMIT();
    }

    float accO[16][4];
#pragma unroll
    for (int nf = 0; nf < 16; nf++)
#pragma unroll
        for (int e = 0; e < 4; e++) accO[nf][e] = 0.f;

    int jt0 = 0;
    {
        float Dh = -45.0f / l2g;
        int jlow = i0 - 31 - (int)Dh;
        if (jlow > 0) jt0 = jlow >> 5;
    }
    const int jtmax = it * 2 + 1;

    for (int jt = jt0; jt <= jtmax; jt++) {
        __syncthreads();
        const int j0 = jt * 32;
        {
            const size_t kb = (size_t)(b * TLEN + j0) * NQK + h * DKh;
#pragma unroll
            for (int u = 0; u < 2; u++) {
                int idx = tid + u * 512;
                int r = idx >> 5, c16 = (idx & 31) * 16;
                uint32_t so = r * 512 + ROWSWZ(r, c16);
                size_t ga = kb + (size_t)r * NQK + (c16 >> 1);
                CP_ASYNC16(sb + RKh + so, Kh + ga);
                CP_ASYNC16(sb + RKl + so, Kl + ga);
            }
            const size_t vb = (size_t)(b * TLEN + j0) * NVG + h * DVh;
#pragma unroll
            for (int u = 0; u < 4; u++) {
                int idx = tid + u * 512;
                int r = idx >> 6, c16 = (idx & 63) * 16;
                uint32_t so = r * 1024 + ROWSWZ(r, c16);
                size_t ga = vb + (size_t)r * NVG + (c16 >> 1);
                CP_ASYNC16(sb + RVh + so, Vh + ga);
                CP_ASYNC16(sb + RVl + so, Vl + ga);
            }
            CP_COMMIT();
        }
        CP_WAIT(0);
        __syncthreads();

        float accS[4] = {0.f, 0.f, 0.f, 0.f};
        {
            const int ar = wm * 16 + (lane & 15);
            const int akb = (lane >> 4) * 16;
            const int br = wn * 8 + (lane & 7);
            const int bkb = ((lane >> 3) & 1) * 16;
            const uint32_t qhb = sb + RQh, qlb = sb + RQl;
            const uint32_t khb = sb + RKh, klb = sb + RKl;
#pragma unroll
            for (int ks = 0; ks < 16; ks++) {
                uint32_t aoff = ar * 512 + ROWSWZ(ar, ks * 32 + akb);
                uint32_t boff = br * 512 + ROWSWZ(br, ks * 32 + bkb);
                uint32_t a0, a1, a2, a3, l0, l1, l2, l3, b0, b1, c0, c1;
                ldmx4(a0, a1, a2, a3, qhb + aoff);
                ldmx2(b0, b1, khb + boff);
                mma16816(accS[0], accS[1], accS[2], accS[3], a0, a1, a2, a3, b0, b1);
                ldmx2(c0, c1, klb + boff);
                mma16816(accS[0], accS[1], accS[2], accS[3], a0, a1, a2, a3, c0, c1);
                ldmx4(l0, l1, l2, l3, qlb + aoff);
                mma16816(accS[0], accS[1], accS[2], accS[3], l0, l1, l2, l3, b0, b1);
            }
        }
        {
            const int il = wm * 16 + (lane >> 2);
            const int jl = wn * 8 + (lane & 3) * 2;
#pragma unroll
            for (int half = 0; half < 2; half++) {
                int r = il + half * 8;
                int d0 = (i0 + r) - (j0 + jl);
                int d1 = d0 - 1;
                float w0 = (d0 >= 0) ? scale * exp2f(l2g * (float)d0) : 0.f;
                float w1 = (d1 >= 0) ? scale * exp2f(l2g * (float)d1) : 0.f;
                float s0 = accS[half * 2 + 0] * w0;
                float s1 = accS[half * 2 + 1] * w1;
                uint32_t so = r * 128 + ROWSWZ(r, jl * 2);
                *(uint32_t*)(smem + RSh + so) = pack_hi(s0, s1);
                *(uint32_t*)(smem + RSl + so) = pack_lo(s0, s1);
            }
        }
        __syncthreads();

        {
            const int ar = wm * 16 + (lane & 15);
            const int akb = (lane >> 4) * 16;
            const uint32_t shb = sb + RSh, slb = sb + RSl;
            const uint32_t vhb = sb + RVh, vlb = sb + RVl;
#pragma unroll
            for (int ks2 = 0; ks2 < 2; ks2++) {
                uint32_t aoff = ar * 128 + ROWSWZ(ar, ks2 * 32 + akb);
                uint32_t s0, s1, s2, s3, t0, t1, t2, t3;
                ldmx4(s0, s1, s2, s3, shb + aoff);
                ldmx4(t0, t1, t2, t3, slb + aoff);
                const int vr = ks2 * 16 + (lane & 15);
#pragma unroll
                for (int nf = 0; nf < 16; nf++) {
                    uint32_t voff = vr * 1024 + ROWSWZ(vr, (wn * 128 + nf * 8) * 2);
                    uint32_t v0, v1, u0, u1;
                    ldmx2t(v0, v1, vhb + voff);
                    mma16816(accO[nf][0], accO[nf][1], accO[nf][2], accO[nf][3],
                             s0, s1, s2, s3, v0, v1);
                    ldmx2t(u0, u1, vlb + voff);
                    mma16816(accO[nf][0], accO[nf][1], accO[nf][2], accO[nf][3],
                             s0, s1, s2, s3, u0, u1);
                    mma16816(accO[nf][0], accO[nf][1], accO[nf][2], accO[nf][3],
                             t0, t1, t2, t3, v0, v1);
                }
            }
        }
    }

    {
        const int il = wm * 16 + (lane >> 2);
        size_t r0 = (size_t)(b * TLEN + i0 + il);
#pragma unroll
        for (int nf = 0; nf < 16; nf++) {
            size_t col = h * DVh + wn * 128 + nf * 8 + (lane & 3) * 2;
            *(float2*)(O + r0 * NVG + col)       = make_float2(accO[nf][0], accO[nf][1]);
            *(float2*)(O + (r0 + 8) * NVG + col) = make_float2(accO[nf][2], accO[nf][3]);
        }
    }
}

// -------- RMS norm + SiLU gate, fused hi/lo split output --------
__global__ __launch_bounds__(256) void rmsgate_split(const float* __restrict__ o,
                                                     const float* __restrict__ g,
                                                     const float* __restrict__ w,
                                                     __nv_bfloat16* __restrict__ oh,
                                                     __nv_bfloat16* __restrict__ ol) {
    int warp = (blockIdx.x * 256 + threadIdx.x) >> 5;
    int lane = threadIdx.x & 31;
    size_t base = (size_t)(warp >> 3) * NVG + (size_t)(warp & 7) * DVh;
    float ov[16];
    float ss = 0.f;
#pragma unroll
    for (int u = 0; u < 16; u++) {
        ov[u] = o[base + lane + u * 32];
        ss += ov[u] * ov[u];
    }
#pragma unroll
    for (int off = 16; off; off >>= 1) ss += __shfl_xor_sync(0xFFFFFFFFu, ss, off);
    float r = rsqrtf(ss * (1.0f / 512.0f) + 1e-5f);
#pragma unroll
    for (int u = 0; u < 16; u++) {
        int c = lane + u * 32;
        float gv = g[base + c];
        float gate = gv / (1.f + expf(-gv));
        float val = ov[u] * r * w[c] * gate;
        __nv_bfloat16 hb = __float2bfloat16(val);
        oh[base + c] = hb;
        ol[base + c] = __float2bfloat16(val - __bfloat162float(hb));
    }
}

extern "C" void kernel_launch(void* const* d_in, const int* in_sizes, int n_in,
                              void* d_out, int out_size) {
    const float* X   = (const float*)d_in[0];
    const float* Wq  = (const float*)d_in[1];
    const float* Wk  = (const float*)d_in[2];
    const float* Wv  = (const float*)d_in[3];
    const float* Wg  = (const float*)d_in[4];
    const float* Wo  = (const float*)d_in[5];
    const float* gnw = (const float*)d_in[6];
    float* out = (float*)d_out;

    unsigned char* pool = nullptr;
    cudaGetSymbolAddress((void**)&pool, g_pool);

    float* dq  = (float*)pool;
    float* dk  = dq  + 8388608;
    float* dv  = dk  + 8388608;                 // unused (kept for layout)
    float* dg  = dv  + 16777216;
    float* dro = dg  + 16777216;
    __nv_bfloat16* bf = (__nv_bfloat16*)(dro + 16777216);
    __nv_bfloat16* Xh   = bf;             __nv_bfloat16* Xl   = Xh   + 8388608;
    __nv_bfloat16* WqTh = Xl   + 8388608; __nv_bfloat16* WqTl = WqTh + 4194304;
    __nv_bfloat16* WkTh = WqTl + 4194304; __nv_bfloat16* WkTl = WkTh + 4194304;
    __nv_bfloat16* WvTh = WkTl + 4194304; __nv_bfloat16* WvTl = WvTh + 8388608;
    __nv_bfloat16* WgTh = WvTl + 8388608; __nv_bfloat16* WgTl = WgTh + 8388608;
    __nv_bfloat16* WoTh = WgTl + 8388608; __nv_bfloat16* WoTl = WoTh + 8388608;
    __nv_bfloat16* droH = WoTl + 8388608; __nv_bfloat16* droL = droH + 16777216;
    __nv_bfloat16* qh   = droL + 16777216; __nv_bfloat16* ql = qh + 8388608;
    __nv_bfloat16* kh   = ql + 8388608;    __nv_bfloat16* kl = kh + 8388608;
    __nv_bfloat16* vh   = kl + 8388608;    __nv_bfloat16* vl = vh + 16777216;

    cudaFuncSetAttribute(gemm_mma<false>, cudaFuncAttributeMaxDynamicSharedMemorySize,
                         GEMM_SMEM);
    cudaFuncSetAttribute(gemm_mma<true>, cudaFuncAttributeMaxDynamicSharedMemorySize,
                         GEMM_SMEM);
    cudaFuncSetAttribute(retention_tc, cudaFuncAttributeMaxDynamicSharedMemorySize,
                         RET_TC_SMEM);

    dim3 thr(256);
    split_k<<<8388608 / 1024, thr>>>(X, Xh, Xl);
    splitT_k<<<dim3(NQK / 32, HID / 32), thr>>>(Wq, WqTh, WqTl, HID, NQK);
    splitT_k<<<dim3(NQK / 32, HID / 32), thr>>>(Wk, WkTh, WkTl, HID, NQK);
    splitT_k<<<dim3(NVG / 32, HID / 32), thr>>>(Wv, WvTh, WvTl, HID, NVG);
    splitT_k<<<dim3(NVG / 32, HID / 32), thr>>>(Wg, WgTh, WgTl, HID, NVG);
    splitT_k<<<dim3(HID / 32, NVG / 32), thr>>>(Wo, WoTh, WoTl, NVG, HID);

    gemm_mma<false><<<dim3(NQK / 128, MTOT / 128), thr, GEMM_SMEM>>>(
        Xh, Xl, WqTh, WqTl, dq, nullptr, nullptr, MTOT, NQK, HID);
    gemm_mma<false><<<dim3(NQK / 128, MTOT / 128), thr, GEMM_SMEM>>>(
        Xh, Xl, WkTh, WkTl, dk, nullptr, nullptr, MTOT, NQK, HID);
    gemm_mma<true><<<dim3(NVG / 128, MTOT / 128), thr, GEMM_SMEM>>>(
        Xh, Xl, WvTh, WvTl, nullptr, vh, vl, MTOT, NVG, HID);
    gemm_mma<false><<<dim3(NVG / 128, MTOT / 128), thr, GEMM_SMEM>>>(
        Xh, Xl, WgTh, WgTl, dg, nullptr, nullptr, MTOT, NVG, HID);

    rope_split<<<16384, 256>>>(dq, dk, qh, ql, kh, kl);

    retention_tc<<<dim3(32, HQ, 2), dim3(512), RET_TC_SMEM>>>(qh, ql, kh, kl, vh, vl, dro);

    rmsgate_split<<<4096, 256>>>(dro, dg, gnw, droH, droL);

    gemm_mma<false><<<dim3(HID / 128, MTOT / 128), thr, GEMM_SMEM>>>(
        droH, droL, WoTh, WoTl, out, nullptr, nullptr, MTOT, HID, NVG);
}

// round 8
// speedup vs baseline: 3.0074x; 1.0567x over previous
#include <cuda_runtime.h>
#include <cuda_bf16.h>
#include <stdint.h>
#include <cstdint>
#include <math.h>

#define MTOT 4096      // B*T
#define TLEN 2048
#define HQ   8
#define DKh  256
#define DVh  512
#define HID  2048
#define NQK  2048      // H*DK
#define NVG  4096      // H*DV

__device__ __align__(1024) unsigned char g_pool[637534208];

__device__ __forceinline__ uint32_t smem_to_u32(const void* p) {
    uint32_t a;
    asm("{ .reg .u64 t; cvta.to.shared.u64 t, %1; cvt.u32.u64 %0, t; }"
        : "=r"(a) : "l"(p));
    return a;
}
#define SMEM_SWIZZLE_128B(byte_offset) \
    ((byte_offset) ^ (((byte_offset) >> 3) & 0x70))
#define ROWSWZ(row, c2) ((c2) ^ (((row) & 7) << 4))

#define CP_ASYNC16(dst_u32, gptr) \
    asm volatile("cp.async.cg.shared.global [%0], [%1], 16;" \
                 :: "r"(dst_u32), "l"(gptr))
#define CP_COMMIT() asm volatile("cp.async.commit_group;" ::: "memory")
#define CP_WAIT(n)  asm volatile("cp.async.wait_group %0;" :: "n"(n) : "memory")

// -------- mma.sync / ldmatrix helpers --------
__device__ __forceinline__ void ldmx4(uint32_t& r0, uint32_t& r1, uint32_t& r2,
                                      uint32_t& r3, uint32_t addr) {
    asm volatile("ldmatrix.sync.aligned.m8n8.x4.shared.b16 {%0,%1,%2,%3}, [%4];"
                 : "=r"(r0), "=r"(r1), "=r"(r2), "=r"(r3) : "r"(addr));
}
__device__ __forceinline__ void ldmx2(uint32_t& r0, uint32_t& r1, uint32_t addr) {
    asm volatile("ldmatrix.sync.aligned.m8n8.x2.shared.b16 {%0,%1}, [%2];"
                 : "=r"(r0), "=r"(r1) : "r"(addr));
}
__device__ __forceinline__ void ldmx2t(uint32_t& r0, uint32_t& r1, uint32_t addr) {
    asm volatile("ldmatrix.sync.aligned.m8n8.x2.trans.shared.b16 {%0,%1}, [%2];"
                 : "=r"(r0), "=r"(r1) : "r"(addr));
}
__device__ __forceinline__ void mma16816(float& c0, float& c1, float& c2, float& c3,
                                         uint32_t a0, uint32_t a1, uint32_t a2,
                                         uint32_t a3, uint32_t b0, uint32_t b1) {
    asm volatile(
        "mma.sync.aligned.m16n8k16.row.col.f32.bf16.bf16.f32 "
        "{%0,%1,%2,%3}, {%4,%5,%6,%7}, {%8,%9}, {%0,%1,%2,%3};"
        : "+f"(c0), "+f"(c1), "+f"(c2), "+f"(c3)
        : "r"(a0), "r"(a1), "r"(a2), "r"(a3), "r"(b0), "r"(b1));
}
__device__ __forceinline__ uint32_t pack_hi(float a, float b) {
    __nv_bfloat16 x = __float2bfloat16(a), y = __float2bfloat16(b);
    return ((uint32_t)*(uint16_t*)&y << 16) | *(uint16_t*)&x;
}
__device__ __forceinline__ uint32_t pack_lo(float a, float b) {
    __nv_bfloat16 x = __float2bfloat16(a), y = __float2bfloat16(b);
    float ra = a - __bfloat162float(x), rb = b - __bfloat162float(y);
    __nv_bfloat16 u = __float2bfloat16(ra), v = __float2bfloat16(rb);
    return ((uint32_t)*(uint16_t*)&v << 16) | *(uint16_t*)&u;
}

// ================= 128x256 HMMA GEMM core, 2-stage cp.async =================
// stage: [Ah 16K][Al 16K][Bh 32K][Bl 32K] = 96KB; 2 stages = 192KB
#define G2_A_BYTES 16384
#define G2_B_BYTES 32768
#define G2_STAGE   98304
#define G2_SMEM    (2 * G2_STAGE)

__device__ __forceinline__ void g256_issue(
    const __nv_bfloat16* pAh, const __nv_bfloat16* pAl,
    const __nv_bfloat16* pBh, const __nv_bfloat16* pBl,
    int kc, uint32_t stg, int tid, int K) {
    {
        const __nv_bfloat16* a0 = pAh + (size_t)kc * 64;
        const __nv_bfloat16* a1 = pAl + (size_t)kc * 64;
#pragma unroll
        for (int u = 0; u < 4; u++) {
            int idx = tid + u * 256;
            int r = idx >> 3, c = idx & 7;
            uint32_t so = SMEM_SWIZZLE_128B(r * 128 + c * 16);
            size_t go = (size_t)r * K + c * 8;
            CP_ASYNC16(stg + so, a0 + go);
            CP_ASYNC16(stg + G2_A_BYTES + so, a1 + go);
        }
    }
    {
        const __nv_bfloat16* b0 = pBh + (size_t)kc * 64;
        const __nv_bfloat16* b1 = pBl + (size_t)kc * 64;
#pragma unroll
        for (int u = 0; u < 8; u++) {
            int idx = tid + u * 256;
            int r = idx >> 3, c = idx & 7;
            uint32_t so = SMEM_SWIZZLE_128B(r * 128 + c * 16);
            size_t go = (size_t)r * K + c * 8;
            CP_ASYNC16(stg + 2 * G2_A_BYTES + so, b0 + go);
            CP_ASYNC16(stg + 2 * G2_A_BYTES + G2_B_BYTES + so, b1 + go);
        }
    }
}

__device__ __forceinline__ void g256_core(
    const __nv_bfloat16* pAh, const __nv_bfloat16* pAl,
    const __nv_bfloat16* pBh, const __nv_bfloat16* pBl,
    int K, int N, size_t aRow, size_t bRow,
    float* C, __nv_bfloat16* Ch, __nv_bfloat16* Cl, char* smem) {
    const uint32_t sb = smem_to_u32(smem);
    const int tid = threadIdx.x;
    const int wid = tid >> 5, lane = tid & 31;
    const int wm = (wid & 1) * 64;
    const int wn = (wid >> 1) * 64;
    const int a_r = lane & 15;
    const int a_k = (lane >> 4) * 8;
    const int b_r = lane & 7;
    const int b_k = ((lane >> 3) & 1) * 8;
    const int KC = K >> 6;

    float acc[4][8][4];
#pragma unroll
    for (int mt = 0; mt < 4; mt++)
#pragma unroll
        for (int nt = 0; nt < 8; nt++)
#pragma unroll
            for (int e = 0; e < 4; e++) acc[mt][nt][e] = 0.f;

    g256_issue(pAh, pAl, pBh, pBl, 0, sb, tid, K);
    CP_COMMIT();
    g256_issue(pAh, pAl, pBh, pBl, 1, sb + G2_STAGE, tid, K);
    CP_COMMIT();

    for (int kc = 0; kc < KC; kc++) {
        if (kc + 1 < KC) { CP_WAIT(1); } else { CP_WAIT(0); }
        __syncthreads();
        const uint32_t base = sb + (kc & 1) * G2_STAGE;
        const uint32_t tAh = base;
        const uint32_t tAl = base + G2_A_BYTES;
        const uint32_t tBh = base + 2 * G2_A_BYTES;
        const uint32_t tBl = base + 2 * G2_A_BYTES + G2_B_BYTES;
#pragma unroll
        for (int ks = 0; ks < 4; ks++) {
            const int k0 = ks * 16;
            uint32_t bh[8][2], bl[8][2];
#pragma unroll
            for (int nt = 0; nt < 8; nt++) {
                int row = wn + nt * 8 + b_r;
                uint32_t off = SMEM_SWIZZLE_128B(row * 128 + (k0 + b_k) * 2);
                ldmx2(bh[nt][0], bh[nt][1], tBh + off);
                ldmx2(bl[nt][0], bl[nt][1], tBl + off);
            }
#pragma unroll
            for (int mt = 0; mt < 4; mt++) {
                int rowA = wm + mt * 16 + a_r;
                uint32_t offA = SMEM_SWIZZLE_128B(rowA * 128 + (k0 + a_k) * 2);
                uint32_t a0, a1, a2, a3;
                ldmx4(a0, a1, a2, a3, tAh + offA);
#pragma unroll
                for (int nt = 0; nt < 8; nt++)
                    mma16816(acc[mt][nt][0], acc[mt][nt][1], acc[mt][nt][2],
                             acc[mt][nt][3], a0, a1, a2, a3, bh[nt][0], bh[nt][1]);
#pragma unroll
                for (int nt = 0; nt < 8; nt++)
                    mma16816(acc[mt][nt][0], acc[mt][nt][1], acc[mt][nt][2],
                             acc[mt][nt][3], a0, a1, a2, a3, bl[nt][0], bl[nt][1]);
                uint32_t l0, l1, l2, l3;
                ldmx4(l0, l1, l2, l3, tAl + offA);
#pragma unroll
                for (int nt = 0; nt < 8; nt++)
                    mma16816(acc[mt][nt][0], acc[mt][nt][1], acc[mt][nt][2],
                             acc[mt][nt][3], l0, l1, l2, l3, bh[nt][0], bh[nt][1]);
            }
        }
        __syncthreads();
        if (kc + 2 < KC) {
            g256_issue(pAh, pAl, pBh, pBl, kc + 2, sb + (kc & 1) * G2_STAGE, tid, K);
            CP_COMMIT();
        }
    }

#pragma unroll
    for (int mt = 0; mt < 4; mt++) {
        size_t m0 = aRow + wm + mt * 16 + (lane >> 2);
#pragma unroll
        for (int nt = 0; nt < 8; nt++) {
            size_t n0 = bRow + wn + nt * 8 + (lane & 3) * 2;
            if (Ch != nullptr) {
                *(uint32_t*)(Ch + m0 * N + n0) = pack_hi(acc[mt][nt][0], acc[mt][nt][1]);
                *(uint32_t*)(Cl + m0 * N + n0) = pack_lo(acc[mt][nt][0], acc[mt][nt][1]);
                *(uint32_t*)(Ch + (m0 + 8) * N + n0) = pack_hi(acc[mt][nt][2], acc[mt][nt][3]);
                *(uint32_t*)(Cl + (m0 + 8) * N + n0) = pack_lo(acc[mt][nt][2], acc[mt][nt][3]);
            } else {
                *(float2*)(C + m0 * N + n0)       = make_float2(acc[mt][nt][0], acc[mt][nt][1]);
                *(float2*)(C + (m0 + 8) * N + n0) = make_float2(acc[mt][nt][2], acc[mt][nt][3]);
            }
        }
    }
}

// combined Q/K/V/G projection launch: blockIdx.x maps to projection + n-tile
__global__ __launch_bounds__(256, 1) void gemm_qkvg(
    const __nv_bfloat16* __restrict__ Xh, const __nv_bfloat16* __restrict__ Xl,
    const __nv_bfloat16* __restrict__ WqTh, const __nv_bfloat16* __restrict__ WqTl,
    const __nv_bfloat16* __restrict__ WkTh, const __nv_bfloat16* __restrict__ WkTl,
    const __nv_bfloat16* __restrict__ WvTh, const __nv_bfloat16* __restrict__ WvTl,
    const __nv_bfloat16* __restrict__ WgTh, const __nv_bfloat16* __restrict__ WgTl,
    float* __restrict__ dq, float* __restrict__ dk, float* __restrict__ dg,
    __nv_bfloat16* __restrict__ vh, __nv_bfloat16* __restrict__ vl) {
    extern __shared__ char smem[];
    int nb = blockIdx.x;
    const __nv_bfloat16 *Bh, *Bl;
    float* C = nullptr;
    __nv_bfloat16 *Ch = nullptr, *Cl = nullptr;
    int N, ntile;
    if (nb < 8)       { Bh = WqTh; Bl = WqTl; C = dq; N = 2048; ntile = nb; }
    else if (nb < 16) { Bh = WkTh; Bl = WkTl; C = dk; N = 2048; ntile = nb - 8; }
    else if (nb < 32) { Bh = WvTh; Bl = WvTl; Ch = vh; Cl = vl; N = 4096; ntile = nb - 16; }
    else              { Bh = WgTh; Bl = WgTl; C = dg; N = 4096; ntile = nb - 32; }
    size_t aRow = (size_t)blockIdx.y * 128;
    size_t bRow = (size_t)ntile * 256;
    g256_core(Xh + aRow * HID, Xl + aRow * HID, Bh + bRow * HID, Bl + bRow * HID,
              HID, N, aRow, bRow, C, Ch, Cl, smem);
}

// generic single GEMM (Wo): C[M,N] = A[M,K] @ B^T, N multiple of 256
__global__ __launch_bounds__(256, 1) void gemm_n256(
    const __nv_bfloat16* __restrict__ Ah, const __nv_bfloat16* __restrict__ Al,
    const __nv_bfloat16* __restrict__ Bh, const __nv_bfloat16* __restrict__ Bl,
    float* __restrict__ C, int N, int K) {
    extern __shared__ char smem[];
    size_t aRow = (size_t)blockIdx.y * 128;
    size_t bRow = (size_t)blockIdx.x * 256;
    g256_core(Ah + aRow * K, Al + aRow * K, Bh + bRow * K, Bl + bRow * K,
              K, N, aRow, bRow, C, nullptr, nullptr, smem);
}

// ------------- fp32 -> bf16 hi/lo split -------------
__global__ __launch_bounds__(256) void split_k(const float* __restrict__ in,
                                               __nv_bfloat16* __restrict__ h,
                                               __nv_bfloat16* __restrict__ l) {
    int i = (blockIdx.x * 256 + threadIdx.x) * 4;
    float4 v = *(const float4*)(in + i);
    float x;
    __nv_bfloat16 hv[4], lv[4];
    x = v.x; hv[0] = __float2bfloat16(x); lv[0] = __float2bfloat16(x - __bfloat162float(hv[0]));
    x = v.y; hv[1] = __float2bfloat16(x); lv[1] = __float2bfloat16(x - __bfloat162float(hv[1]));
    x = v.z; hv[2] = __float2bfloat16(x); lv[2] = __float2bfloat16(x - __bfloat162float(hv[2]));
    x = v.w; hv[3] = __float2bfloat16(x); lv[3] = __float2bfloat16(x - __bfloat162float(hv[3]));
    *(uint2*)(h + i) = *(uint2*)hv;
    *(uint2*)(l + i) = *(uint2*)lv;
}

// ------------- fp32 [K,N] -> bf16 hi/lo transposed [N,K] -------------
__global__ __launch_bounds__(256) void splitT_k(const float* __restrict__ in,
                                                __nv_bfloat16* __restrict__ hT,
                                                __nv_bfloat16* __restrict__ lT,
                                                int K, int N) {
    __shared__ float ts[32][33];
    int n0 = blockIdx.x * 32, k0 = blockIdx.y * 32;
    int tx = threadIdx.x & 31, ty = threadIdx.x >> 5;
#pragma unroll
    for (int r = 0; r < 4; r++)
        ts[ty + r * 8][tx] = in[(size_t)(k0 + ty + r * 8) * N + n0 + tx];
    __syncthreads();
#pragma unroll
    for (int r = 0; r < 4; r++) {
        int n = n0 + ty + r * 8, kk = k0 + tx;
        float x = ts[tx][ty + r * 8];
        __nv_bfloat16 hi = __float2bfloat16(x);
        hT[(size_t)n * K + kk] = hi;
        lT[(size_t)n * K + kk] = __float2bfloat16(x - __bfloat162float(hi));
    }
}

// ---------------- fused RoPE + hi/lo split ----------------
__global__ __launch_bounds__(256) void rope_split(const float* __restrict__ q,
                                                  const float* __restrict__ k,
                                                  __nv_bfloat16* __restrict__ qh,
                                                  __nv_bfloat16* __restrict__ ql,
                                                  __nv_bfloat16* __restrict__ kh,
                                                  __nv_bfloat16* __restrict__ kl) {
    int idx = blockIdx.x * 256 + threadIdx.x;
    int j  = idx & 127;
    int h  = (idx >> 7) & 7;
    int bt = idx >> 10;
    int pos = bt & (TLEN - 1);
    float inv = exp2f(-(float)j * (13.2877123795494f / 128.0f));
    float ph = (float)pos * inv;
    float s, c;
    sincosf(ph, &s, &c);
    size_t base = (size_t)bt * NQK + h * DKh + j;

    float x1 = q[base], x2 = q[base + 128];
    float o1 = x1 * c - x2 * s, o2 = x2 * c + x1 * s;
    __nv_bfloat16 hb = __float2bfloat16(o1);
    qh[base] = hb; ql[base] = __float2bfloat16(o1 - __bfloat162float(hb));
    hb = __float2bfloat16(o2);
    qh[base + 128] = hb; ql[base + 128] = __float2bfloat16(o2 - __bfloat162float(hb));

    x1 = k[base]; x2 = k[base + 128];
    o1 = x1 * c - x2 * s; o2 = x2 * c + x1 * s;
    hb = __float2bfloat16(o1);
    kh[base] = hb; kl[base] = __float2bfloat16(o1 - __bfloat162float(hb));
    hb = __float2bfloat16(o2);
    kh[base + 128] = hb; kl[base + 128] = __float2bfloat16(o2 - __bfloat162float(hb));
}

// ============ Tensor-core retention, pipelined K/V loads ============
// smem: Qh 0(32K) Ql 32K | Kh 64K(16K) Kl 80K | V0h 96K(16K) V0l 112K
//       V1h 128K(16K) V1l 144K | Sh 160K(8K) Sl 168K   -> 176KB
#define RQh  0
#define RQl  32768
#define RKh  65536
#define RKl  81920
#define RV0h 98304
#define RV0l 114688
#define RV1h 131072
#define RV1l 147456
#define RSh  163840
#define RSl  172032
#define RET_TC_SMEM 180224

__device__ __forceinline__ void ret_issue_K(uint32_t sb, int tid,
                                            const __nv_bfloat16* Kh,
                                            const __nv_bfloat16* Kl, size_t kb) {
#pragma unroll
    for (int u = 0; u < 2; u++) {
        int idx = tid + u * 512;
        int r = idx >> 5, c16 = (idx & 31) * 16;
        uint32_t so = r * 512 + ROWSWZ(r, c16);
        size_t ga = kb + (size_t)r * NQK + (c16 >> 1);
        CP_ASYNC16(sb + RKh + so, Kh + ga);
        CP_ASYNC16(sb + RKl + so, Kl + ga);
    }
}
__device__ __forceinline__ void ret_issue_Vhalf(uint32_t sb, int tid,
                                                const __nv_bfloat16* Vh,
                                                const __nv_bfloat16* Vl,
                                                size_t vb, int hf, uint32_t bufh,
                                                uint32_t bufl) {
#pragma unroll
    for (int u = 0; u < 2; u++) {
        int idx = tid + u * 512;
        int r = idx >> 6, c16 = (idx & 63) * 16;
        uint32_t so = r * 1024 + ROWSWZ(r, c16);
        size_t ga = vb + (size_t)(hf * 16 + r) * NVG + (c16 >> 1);
        CP_ASYNC16(sb + bufh + so, Vh + ga);
        CP_ASYNC16(sb + bufl + so, Vl + ga);
    }
}
__device__ __forceinline__ void ret_sv_half(uint32_t sb, int lane, int wm, int wn,
                                            int ks2, uint32_t vbh, uint32_t vbl,
                                            float accO[16][4]) {
    const int ar = wm * 16 + (lane & 15);
    const int akb = (lane >> 4) * 16;
    uint32_t aoff = ar * 128 + ROWSWZ(ar, ks2 * 32 + akb);
    uint32_t s0, s1, s2, s3, t0, t1, t2, t3;
    ldmx4(s0, s1, s2, s3, sb + RSh + aoff);
    ldmx4(t0, t1, t2, t3, sb + RSl + aoff);
    const int vr = lane & 15;
#pragma unroll
    for (int nf = 0; nf < 16; nf++) {
        uint32_t voff = vr * 1024 + ROWSWZ(vr, (wn * 128 + nf * 8) * 2);
        uint32_t v0, v1, u0, u1;
        ldmx2t(v0, v1, sb + vbh + voff);
        mma16816(accO[nf][0], accO[nf][1], accO[nf][2], accO[nf][3],
                 s0, s1, s2, s3, v0, v1);
        ldmx2t(u0, u1, sb + vbl + voff);
        mma16816(accO[nf][0], accO[nf][1], accO[nf][2], accO[nf][3],
                 s0, s1, s2, s3, u0, u1);
        mma16816(accO[nf][0], accO[nf][1], accO[nf][2], accO[nf][3],
                 t0, t1, t2, t3, v0, v1);
    }
}

__global__ __launch_bounds__(512, 1) void retention_tc(
    const __nv_bfloat16* __restrict__ Qh, const __nv_bfloat16* __restrict__ Ql,
    const __nv_bfloat16* __restrict__ Kh, const __nv_bfloat16* __restrict__ Kl,
    const __nv_bfloat16* __restrict__ Vh, const __nv_bfloat16* __restrict__ Vl,
    float* __restrict__ O) {
    extern __shared__ char smem[];
    const uint32_t sb = smem_to_u32(smem);
    const int tid  = threadIdx.x;
    const int wid  = tid >> 5, lane = tid & 31;
    const int wm   = wid & 3;
    const int wn   = wid >> 2;

    const int it = 31 - blockIdx.x;
    const int h  = blockIdx.y;
    const int b  = blockIdx.z;
    const int i0 = it * 64;
    const float scale = 0.0625f;
    const float gamma = 1.0f - exp2f(-5.0f - (float)h);
    const float l2g   = log2f(gamma);

    const size_t kbase = (size_t)(b * TLEN) * NQK + h * DKh;
    const size_t vbase = (size_t)(b * TLEN) * NVG + h * DVh;

    int jt0 = 0;
    {
        float Dh = -45.0f / l2g;
        int jlow = i0 - 31 - (int)Dh;
        if (jlow > 0) jt0 = jlow >> 5;
    }
    const int jtmax = it * 2 + 1;

    // prologue: Q + K(jt0) in one group, then V halves
    {
        const size_t qb = (size_t)(b * TLEN + i0) * NQK + h * DKh;
#pragma unroll
        for (int u = 0; u < 4; u++) {
            int idx = tid + u * 512;
            int r = idx >> 5, c16 = (idx & 31) * 16;
            uint32_t so = r * 512 + ROWSWZ(r, c16);
            size_t ga = qb + (size_t)r * NQK + (c16 >> 1);
            CP_ASYNC16(sb + RQh + so, Qh + ga);
            CP_ASYNC16(sb + RQl + so, Ql + ga);
        }
        ret_issue_K(sb, tid, Kh, Kl, kbase + (size_t)(jt0 * 32) * NQK);
        CP_COMMIT();
        ret_issue_Vhalf(sb, tid, Vh, Vl, vbase + (size_t)(jt0 * 32) * NVG, 0, RV0h, RV0l);
        CP_COMMIT();
        ret_issue_Vhalf(sb, tid, Vh, Vl, vbase + (size_t)(jt0 * 32) * NVG, 1, RV1h, RV1l);
        CP_COMMIT();
    }

    float accO[16][4];
#pragma unroll
    for (int nf = 0; nf < 16; nf++)
#pragma unroll
        for (int e = 0; e < 4; e++) accO[nf][e] = 0.f;

    for (int jt = jt0; jt <= jtmax; jt++) {
        const int j0 = jt * 32;
        const int jn = (jt + 1 <= jtmax) ? (jt + 1) : jtmax;   // clamped prefetch

        CP_WAIT(2);             // Q(first)+K(jt) ready
        __syncthreads();

        // ---- S = Q K^T (3-term) ----
        float accS[4] = {0.f, 0.f, 0.f, 0.f};
        {
            const int ar = wm * 16 + (lane & 15);
            const int akb = (lane >> 4) * 16;
            const int br = wn * 8 + (lane & 7);
            const int bkb = ((lane >> 3) & 1) * 16;
#pragma unroll
            for (int ks = 0; ks < 16; ks++) {
                uint32_t aoff = ar * 512 + ROWSWZ(ar, ks * 32 + akb);
                uint32_t boff = br * 512 + ROWSWZ(br, ks * 32 + bkb);
                uint32_t a0, a1, a2, a3, l0, l1, l2, l3, b0, b1, c0, c1;
                ldmx4(a0, a1, a2, a3, sb + RQh + aoff);
                ldmx2(b0, b1, sb + RKh + boff);
                mma16816(accS[0], accS[1], accS[2], accS[3], a0, a1, a2, a3, b0, b1);
                ldmx2(c0, c1, sb + RKl + boff);
                mma16816(accS[0], accS[1], accS[2], accS[3], a0, a1, a2, a3, c0, c1);
                ldmx4(l0, l1, l2, l3, sb + RQl + aoff);
                mma16816(accS[0], accS[1], accS[2], accS[3], l0, l1, l2, l3, b0, b1);
            }
        }
        // ---- decay + mask + split store ----
        {
            const int il = wm * 16 + (lane >> 2);
            const int jl = wn * 8 + (lane & 3) * 2;
#pragma unroll
            for (int half = 0; half < 2; half++) {
                int r = il + half * 8;
                int d0 = (i0 + r) - (j0 + jl);
                int d1 = d0 - 1;
                float w0 = (d0 >= 0) ? scale * exp2f(l2g * (float)d0) : 0.f;
                float w1 = (d1 >= 0) ? scale * exp2f(l2g * (float)d1) : 0.f;
                float s0 = accS[half * 2 + 0] * w0;
                float s1 = accS[half * 2 + 1] * w1;
                uint32_t so = r * 128 + ROWSWZ(r, jl * 2);
                *(uint32_t*)(smem + RSh + so) = pack_hi(s0, s1);
                *(uint32_t*)(smem + RSl + so) = pack_lo(s0, s1);
            }
        }
        __syncthreads();                                  // S visible; K reads done
        ret_issue_K(sb, tid, Kh, Kl, kbase + (size_t)(jn * 32) * NQK);
        CP_COMMIT();

        CP_WAIT(2);                                       // V(jt, half0) ready
        __syncthreads();
        ret_sv_half(sb, lane, wm, wn, 0, RV0h, RV0l, accO);
        __syncthreads();                                  // done reading buf0
        ret_issue_Vhalf(sb, tid, Vh, Vl, vbase + (size_t)(jn * 32) * NVG, 0, RV0h, RV0l);
        CP_COMMIT();

        CP_WAIT(2);                                       // V(jt, half1) ready
        __syncthreads();
        ret_sv_half(sb, lane, wm, wn, 1, RV1h, RV1l, accO);
        __syncthreads();                                  // done reading buf1
        ret_issue_Vhalf(sb, tid, Vh, Vl, vbase + (size_t)(jn * 32) * NVG, 1, RV1h, RV1l);
        CP_COMMIT();
    }
    CP_WAIT(0);
    __syncthreads();

    // ---- write O tile ----
    {
        const int il = wm * 16 + (lane >> 2);
        size_t r0 = (size_t)(b * TLEN + i0 + il);
#pragma unroll
        for (int nf = 0; nf < 16; nf++) {
            size_t col = h * DVh + wn * 128 + nf * 8 + (lane & 3) * 2;
            *(float2*)(O + r0 * NVG + col)       = make_float2(accO[nf][0], accO[nf][1]);
            *(float2*)(O + (r0 + 8) * NVG + col) = make_float2(accO[nf][2], accO[nf][3]);
        }
    }
}

// -------- RMS norm + SiLU gate, fused hi/lo split output --------
__global__ __launch_bounds__(256) void rmsgate_split(const float* __restrict__ o,
                                                     const float* __restrict__ g,
                                                     const float* __restrict__ w,
                                                     __nv_bfloat16* __restrict__ oh,
                                                     __nv_bfloat16* __restrict__ ol) {
    int warp = (blockIdx.x * 256 + threadIdx.x) >> 5;
    int lane = threadIdx.x & 31;
    size_t base = (size_t)(warp >> 3) * NVG + (size_t)(warp & 7) * DVh;
    float ov[16];
    float ss = 0.f;
#pragma unroll
    for (int u = 0; u < 16; u++) {
        ov[u] = o[base + lane + u * 32];
        ss += ov[u] * ov[u];
    }
#pragma unroll
    for (int off = 16; off; off >>= 1) ss += __shfl_xor_sync(0xFFFFFFFFu, ss, off);
    float r = rsqrtf(ss * (1.0f / 512.0f) + 1e-5f);
#pragma unroll
    for (int u = 0; u < 16; u++) {
        int c = lane + u * 32;
        float gv = g[base + c];
        float gate = gv / (1.f + expf(-gv));
        float val = ov[u] * r * w[c] * gate;
        __nv_bfloat16 hb = __float2bfloat16(val);
        oh[base + c] = hb;
        ol[base + c] = __float2bfloat16(val - __bfloat162float(hb));
    }
}

extern "C" void kernel_launch(void* const* d_in, const int* in_sizes, int n_in,
                              void* d_out, int out_size) {
    const float* X   = (const float*)d_in[0];
    const float* Wq  = (const float*)d_in[1];
    const float* Wk  = (const float*)d_in[2];
    const float* Wv  = (const float*)d_in[3];
    const float* Wg  = (const float*)d_in[4];
    const float* Wo  = (const float*)d_in[5];
    const float* gnw = (const float*)d_in[6];
    float* out = (float*)d_out;

    unsigned char* pool = nullptr;
    cudaGetSymbolAddress((void**)&pool, g_pool);

    float* dq  = (float*)pool;
    float* dk  = dq  + 8388608;
    float* dv  = dk  + 8388608;                 // unused slot
    float* dg  = dv  + 16777216;
    float* dro = dg  + 16777216;
    __nv_bfloat16* bf = (__nv_bfloat16*)(dro + 16777216);
    __nv_bfloat16* Xh   = bf;             __nv_bfloat16* Xl   = Xh   + 8388608;
    __nv_bfloat16* WqTh = Xl   + 8388608; __nv_bfloat16* WqTl = WqTh + 4194304;
    __nv_bfloat16* WkTh = WqTl + 4194304; __nv_bfloat16* WkTl = WkTh + 4194304;
    __nv_bfloat16* WvTh = WkTl + 4194304; __nv_bfloat16* WvTl = WvTh + 8388608;
    __nv_bfloat16* WgTh = WvTl + 8388608; __nv_bfloat16* WgTl = WgTh + 8388608;
    __nv_bfloat16* WoTh = WgTl + 8388608; __nv_bfloat16* WoTl = WoTh + 8388608;
    __nv_bfloat16* droH = WoTl + 8388608; __nv_bfloat16* droL = droH + 16777216;
    __nv_bfloat16* qh   = droL + 16777216; __nv_bfloat16* ql = qh + 8388608;
    __nv_bfloat16* kh   = ql + 8388608;    __nv_bfloat16* kl = kh + 8388608;
    __nv_bfloat16* vh   = kl + 8388608;    __nv_bfloat16* vl = vh + 16777216;

    cudaFuncSetAttribute(gemm_qkvg, cudaFuncAttributeMaxDynamicSharedMemorySize, G2_SMEM);
    cudaFuncSetAttribute(gemm_n256, cudaFuncAttributeMaxDynamicSharedMemorySize, G2_SMEM);
    cudaFuncSetAttribute(retention_tc, cudaFuncAttributeMaxDynamicSharedMemorySize,
                         RET_TC_SMEM);

    dim3 thr(256);
    split_k<<<8388608 / 1024, thr>>>(X, Xh, Xl);
    splitT_k<<<dim3(NQK / 32, HID / 32), thr>>>(Wq, WqTh, WqTl, HID, NQK);
    splitT_k<<<dim3(NQK / 32, HID / 32), thr>>>(Wk, WkTh, WkTl, HID, NQK);
    splitT_k<<<dim3(NVG / 32, HID / 32), thr>>>(Wv, WvTh, WvTl, HID, NVG);
    splitT_k<<<dim3(NVG / 32, HID / 32), thr>>>(Wg, WgTh, WgTl, HID, NVG);
    splitT_k<<<dim3(HID / 32, NVG / 32), thr>>>(Wo, WoTh, WoTl, NVG, HID);

    // all four projections in one launch (48 n-tiles x 32 m-tiles)
    gemm_qkvg<<<dim3(48, 32), thr, G2_SMEM>>>(Xh, Xl, WqTh, WqTl, WkTh, WkTl,
                                              WvTh, WvTl, WgTh, WgTl,
                                              dq, dk, dg, vh, vl);

    rope_split<<<16384, 256>>>(dq, dk, qh, ql, kh, kl);

    retention_tc<<<dim3(32, HQ, 2), dim3(512), RET_TC_SMEM>>>(qh, ql, kh, kl, vh, vl, dro);

    rmsgate_split<<<4096, 256>>>(dro, dg, gnw, droH, droL);

    gemm_n256<<<dim3(HID / 256, MTOT / 128), thr, G2_SMEM>>>(droH, droL, WoTh, WoTl,
                                                             out, HID, NVG);
}